// round 1
// baseline (speedup 1.0000x reference)
#include <cuda_runtime.h>
#include <cuda_bf16.h>
#include <math.h>

// ---------------- problem constants ----------------
#define BATCH 2
#define SEQ   2048
#define DM    1024
#define NH    16
#define DH    64
#define NTOK  (BATCH*SEQ)        // 4096
#define CHUNK 128
#define NCH   (SEQ/CHUNK)        // 16
#define NBH   (BATCH*NH)         // 32

// ---------------- scratch (device globals; no allocs allowed) ----------------
__device__ float g_xnorm[NTOK*DM];
__device__ float g_qkv  [NTOK*3*DM];
__device__ float g_gate [NTOK*DM];
__device__ float g_qh   [NBH*SEQ*DH];
__device__ float g_kh   [NBH*SEQ*DH];
__device__ float g_vh   [NBH*SEQ*DH];
__device__ float g_kv   [NBH*NCH*DH*DH];
__device__ float g_kvpre[NBH*NCH*DH*DH];
__device__ float g_ksum [NBH*NCH*DH];
__device__ float g_kspre[NBH*NCH*DH];
__device__ float g_ctx  [NTOK*DM];

// ---------------- LayerNorm: one block per token row ----------------
__global__ void ln_kernel(const float* __restrict__ x, const float* __restrict__ g,
                          const float* __restrict__ bta, float* __restrict__ xn) {
    __shared__ float red0[8], red1[8];
    int row = blockIdx.x, tid = threadIdx.x;   // 256 threads, 4 floats each
    const float* xr = x + (size_t)row * DM;
    float4 xv = *(const float4*)(xr + tid * 4);
    float s  = xv.x + xv.y + xv.z + xv.w;
    float s2 = xv.x*xv.x + xv.y*xv.y + xv.z*xv.z + xv.w*xv.w;
    #pragma unroll
    for (int o = 16; o > 0; o >>= 1) {
        s  += __shfl_xor_sync(0xffffffffu, s,  o);
        s2 += __shfl_xor_sync(0xffffffffu, s2, o);
    }
    int w = tid >> 5;
    if ((tid & 31) == 0) { red0[w] = s; red1[w] = s2; }
    __syncthreads();
    if (tid < 32) {
        s  = (tid < 8) ? red0[tid] : 0.f;
        s2 = (tid < 8) ? red1[tid] : 0.f;
        #pragma unroll
        for (int o = 4; o > 0; o >>= 1) {
            s  += __shfl_xor_sync(0xffffffffu, s,  o);
            s2 += __shfl_xor_sync(0xffffffffu, s2, o);
        }
        if (tid == 0) { red0[0] = s; red1[0] = s2; }
    }
    __syncthreads();
    float mu   = red0[0] * (1.f / DM);
    float var  = red1[0] * (1.f / DM) - mu * mu;
    float rstd = rsqrtf(var + 1e-5f);
    float4 gv = *(const float4*)(g + tid * 4);
    float4 bv = *(const float4*)(bta + tid * 4);
    float4 o4;
    o4.x = (xv.x - mu) * rstd * gv.x + bv.x;
    o4.y = (xv.y - mu) * rstd * gv.y + bv.y;
    o4.z = (xv.z - mu) * rstd * gv.z + bv.z;
    o4.w = (xv.w - mu) * rstd * gv.w + bv.w;
    *(float4*)(xn + (size_t)row * DM + tid * 4) = o4;
}

// ---------------- generic fp32 GEMM: C = A[MxK] @ B[KxN] + bias, optional sigmoid ----
// BM=BN=128, BK=16, 256 threads, 8x8 per thread
template<bool SIGMOID>
__global__ void gemm_kernel(const float* __restrict__ A, const float* __restrict__ B,
                            const float* __restrict__ bias, float* __restrict__ C,
                            int M, int N, int K) {
    __shared__ float As[16][128];
    __shared__ float Bs[16][128];
    int tid = threadIdx.x;
    int bm = blockIdx.y, bn = blockIdx.x;
    const float* Ab = A + (size_t)bm * 128 * K;
    const float* Bb = B + (size_t)bn * 128;
    float acc[8][8];
    #pragma unroll
    for (int i = 0; i < 8; i++)
        #pragma unroll
        for (int j = 0; j < 8; j++) acc[i][j] = 0.f;
    int tm = tid >> 4, tn = tid & 15;

    for (int k0 = 0; k0 < K; k0 += 16) {
        #pragma unroll
        for (int l = 0; l < 2; l++) {
            int id = tid * 2 + l;                 // 0..511
            int ar = id >> 2, ac = (id & 3) * 4;  // A: 128 rows x 16 cols
            float4 av = *(const float4*)(Ab + (size_t)ar * K + k0 + ac);
            As[ac + 0][ar] = av.x; As[ac + 1][ar] = av.y;
            As[ac + 2][ar] = av.z; As[ac + 3][ar] = av.w;
            int br = id >> 5, bc = (id & 31) * 4; // B: 16 rows x 128 cols
            float4 bv = *(const float4*)(Bb + (size_t)(k0 + br) * N + bc);
            *(float4*)&Bs[br][bc] = bv;
        }
        __syncthreads();
        #pragma unroll
        for (int kk = 0; kk < 16; kk++) {
            float a[8], b[8];
            *(float4*)&a[0] = *(const float4*)&As[kk][tm * 8];
            *(float4*)&a[4] = *(const float4*)&As[kk][tm * 8 + 4];
            *(float4*)&b[0] = *(const float4*)&Bs[kk][tn * 8];
            *(float4*)&b[4] = *(const float4*)&Bs[kk][tn * 8 + 4];
            #pragma unroll
            for (int i = 0; i < 8; i++)
                #pragma unroll
                for (int j = 0; j < 8; j++) acc[i][j] += a[i] * b[j];
        }
        __syncthreads();
    }
    #pragma unroll
    for (int i = 0; i < 8; i++) {
        int row = bm * 128 + tm * 8 + i;
        #pragma unroll
        for (int j = 0; j < 8; j += 4) {
            int col = bn * 128 + tn * 8 + j;
            float4 o;
            o.x = acc[i][j + 0] + bias[col + 0];
            o.y = acc[i][j + 1] + bias[col + 1];
            o.z = acc[i][j + 2] + bias[col + 2];
            o.w = acc[i][j + 3] + bias[col + 3];
            if (SIGMOID) {
                o.x = 1.f / (1.f + expf(-o.x));
                o.y = 1.f / (1.f + expf(-o.y));
                o.z = 1.f / (1.f + expf(-o.z));
                o.w = 1.f / (1.f + expf(-o.w));
            }
            *(float4*)(C + (size_t)row * N + col) = o;
        }
    }
}

// ---------------- gate normalize (in place): g /= (rowmean(g)+1e-5) ----------------
__global__ void gate_norm_kernel(float* __restrict__ gate) {
    __shared__ float red[8];
    int row = blockIdx.x, tid = threadIdx.x;
    float* gr = gate + (size_t)row * DM;
    float4 gv = *(const float4*)(gr + tid * 4);
    float s = gv.x + gv.y + gv.z + gv.w;
    #pragma unroll
    for (int o = 16; o > 0; o >>= 1) s += __shfl_xor_sync(0xffffffffu, s, o);
    if ((tid & 31) == 0) red[tid >> 5] = s;
    __syncthreads();
    if (tid < 32) {
        s = (tid < 8) ? red[tid] : 0.f;
        #pragma unroll
        for (int o = 4; o > 0; o >>= 1) s += __shfl_xor_sync(0xffffffffu, s, o);
        if (tid == 0) red[0] = s;
    }
    __syncthreads();
    float scale = 1.f / (red[0] * (1.f / DM) + 1e-5f);
    gv.x *= scale; gv.y *= scale; gv.z *= scale; gv.w *= scale;
    *(float4*)(gr + tid * 4) = gv;
}

// ---------------- split qkv into head layout; apply gate and elu+1 ----------------
__global__ void split_kernel() {
    int idx = blockIdx.x * blockDim.x + threadIdx.x;   // over NTOK*DM
    if (idx >= NTOK * DM) return;
    int n = idx >> 10, cix = idx & 1023;
    int h = cix >> 6, e = cix & 63;
    int b = n >> 11, t = n & 2047;
    float gn = g_gate[idx];
    float qv = g_qkv[(size_t)n * 3072 + cix] * gn;
    float kv = g_qkv[(size_t)n * 3072 + 1024 + cix] * gn;
    float vv = g_qkv[(size_t)n * 3072 + 2048 + cix];
    qv = (qv > 0.f) ? qv + 1.f : expf(qv);   // elu(x)+1
    kv = (kv > 0.f) ? kv + 1.f : expf(kv);
    int o = ((b * NH + h) * SEQ + t) * DH + e;
    g_qh[o] = qv; g_kh[o] = kv; g_vh[o] = vv;
}

// ---------------- pass A: per-chunk KV = k^T@v [64x64], ksum[64] ----------------
__global__ void passA_kernel() {
    __shared__ float ks[64][64];
    __shared__ float vs[64][64];
    int blk = blockIdx.x;                       // NBH*NCH = 512
    int bh = blk / NCH, c = blk % NCH;
    const float* kb = g_kh + ((size_t)bh * SEQ + c * CHUNK) * DH;
    const float* vb = g_vh + ((size_t)bh * SEQ + c * CHUNK) * DH;
    int tid = threadIdx.x;                      // 256
    int d = tid & 63, mg = tid >> 6;            // 4 groups of 16 m's
    float acc[16];
    #pragma unroll
    for (int i = 0; i < 16; i++) acc[i] = 0.f;
    float ksum = 0.f;
    for (int half = 0; half < 2; half++) {
        __syncthreads();
        #pragma unroll
        for (int l = 0; l < 4; l++) {
            int id = tid + l * 256;             // 1024 float4 covers 4096 floats
            int r = id >> 4, c4 = (id & 15) * 4;
            *(float4*)&ks[r][c4] = *(const float4*)(kb + half * 64 * 64 + r * 64 + c4);
            *(float4*)&vs[r][c4] = *(const float4*)(vb + half * 64 * 64 + r * 64 + c4);
        }
        __syncthreads();
        #pragma unroll 4
        for (int t = 0; t < 64; t++) {
            float kd = ks[t][d];
            if (mg == 0) ksum += kd;
            #pragma unroll
            for (int i = 0; i < 16; i++) acc[i] += kd * vs[t][mg * 16 + i];
        }
    }
    float* kvo = g_kv + (size_t)blk * (DH * DH);
    #pragma unroll
    for (int i = 0; i < 16; i += 4)
        *(float4*)(kvo + d * 64 + mg * 16 + i) = make_float4(acc[i], acc[i+1], acc[i+2], acc[i+3]);
    if (mg == 0) g_ksum[blk * DH + d] = ksum;
}

// ---------------- pass B: exclusive prefix over chunks per (b,h) ----------------
__global__ void passB_kernel() {
    int bh = blockIdx.x;                        // 32
    int tid = threadIdx.x;                      // 256
    #pragma unroll
    for (int l = 0; l < 16; l++) {
        int e = tid + l * 256;                  // 4096 elems
        float run = 0.f;
        for (int c = 0; c < NCH; c++) {
            size_t idx = ((size_t)bh * NCH + c) * (DH * DH) + e;
            g_kvpre[idx] = run;
            run += g_kv[idx];
        }
    }
    if (tid < DH) {
        float run = 0.f;
        for (int c = 0; c < NCH; c++) {
            size_t idx = ((size_t)bh * NCH + c) * DH + tid;
            g_kspre[idx] = run;
            run += g_ksum[idx];
        }
    }
}

// ---------------- pass C: out = (q@S_pre + intra-causal(q,k,v)) / den ----------------
__global__ void passC_kernel() {
    extern __shared__ float sm[];
    float (*k_sm)[64] = (float(*)[64])sm;                  // 128x64
    float (*v_sm)[64] = (float(*)[64])(sm + 128 * 64);     // 128x64
    float (*s_sm)[64] = (float(*)[64])(sm + 2 * 128 * 64); // 64x64
    float* kp_sm = sm + 2 * 128 * 64 + 64 * 64;            // 64

    int blk = blockIdx.x;                       // 512
    int bh = blk / NCH, c = blk % NCH;
    int b = bh / NH, h = bh % NH;
    int tid = threadIdx.x;                      // 256
    const float* qb = g_qh + ((size_t)bh * SEQ + c * CHUNK) * DH;
    const float* kb = g_kh + ((size_t)bh * SEQ + c * CHUNK) * DH;
    const float* vb = g_vh + ((size_t)bh * SEQ + c * CHUNK) * DH;

    #pragma unroll
    for (int l = 0; l < 8; l++) {
        int id = tid + l * 256;                 // 2048 float4 -> 8192 floats
        int r = id >> 4, c4 = (id & 15) * 4;
        *(float4*)&k_sm[r][c4] = *(const float4*)(kb + r * 64 + c4);
        *(float4*)&v_sm[r][c4] = *(const float4*)(vb + r * 64 + c4);
    }
    #pragma unroll
    for (int l = 0; l < 4; l++) {
        int id = tid + l * 256;                 // 1024 float4 -> 4096 floats
        int r = id >> 4, c4 = (id & 15) * 4;
        *(float4*)&s_sm[r][c4] = *(const float4*)(g_kvpre + (size_t)blk * 4096 + r * 64 + c4);
    }
    if (tid < 64) kp_sm[tid] = g_kspre[(size_t)blk * 64 + tid];
    __syncthreads();

    int t = tid >> 1, half = tid & 1;           // 2 threads per row; m = half + 2*i
    float q[64];
    #pragma unroll
    for (int i = 0; i < 64; i += 4) {
        float4 qv = *(const float4*)(qb + t * 64 + i);
        q[i] = qv.x; q[i+1] = qv.y; q[i+2] = qv.z; q[i+3] = qv.w;
    }
    float acc[32];
    #pragma unroll
    for (int i = 0; i < 32; i++) acc[i] = 0.f;
    float den = 0.f;

    // inter-chunk: q @ S_pre, q . kspre
    #pragma unroll 8
    for (int d = 0; d < 64; d++) {
        float qd = q[d];
        den += qd * kp_sm[d];
        #pragma unroll
        for (int i = 0; i < 32; i++) acc[i] += qd * s_sm[d][half + 2 * i];
    }
    // intra-chunk causal
    for (int s = 0; s <= t; s++) {
        float a = 0.f;
        #pragma unroll
        for (int d = 0; d < 64; d++) a += q[d] * k_sm[s][d];
        den += a;
        #pragma unroll
        for (int i = 0; i < 32; i++) acc[i] += a * v_sm[s][half + 2 * i];
    }
    float inv = 1.f / (den + 1e-5f);
    int token = b * SEQ + c * CHUNK + t;
    float* outp = g_ctx + (size_t)token * DM + h * DH;
    #pragma unroll
    for (int i = 0; i < 32; i++) outp[half + 2 * i] = acc[i] * inv;
}

// ---------------- launch ----------------
extern "C" void kernel_launch(void* const* d_in, const int* in_sizes, int n_in,
                              void* d_out, int out_size) {
    const float* x      = (const float*)d_in[0];
    const float* ln_g   = (const float*)d_in[1];
    const float* ln_b   = (const float*)d_in[2];
    const float* w_qkv  = (const float*)d_in[3];
    const float* b_qkv  = (const float*)d_in[4];
    const float* w_gate = (const float*)d_in[5];
    const float* b_gate = (const float*)d_in[6];
    const float* w_proj = (const float*)d_in[7];
    const float* b_proj = (const float*)d_in[8];
    float* out = (float*)d_out;

    float *p_xnorm, *p_qkv, *p_gate, *p_ctx;
    cudaGetSymbolAddress((void**)&p_xnorm, g_xnorm);
    cudaGetSymbolAddress((void**)&p_qkv,   g_qkv);
    cudaGetSymbolAddress((void**)&p_gate,  g_gate);
    cudaGetSymbolAddress((void**)&p_ctx,   g_ctx);

    const int smemC = (2 * 128 * 64 + 64 * 64 + 64) * 4;  // 82176 B
    cudaFuncSetAttribute(passC_kernel, cudaFuncAttributeMaxDynamicSharedMemorySize, smemC);

    // 1. LayerNorm
    ln_kernel<<<NTOK, 256>>>(x, ln_g, ln_b, p_xnorm);
    // 2. qkv = xnorm @ w_qkv + b_qkv
    gemm_kernel<false><<<dim3(3 * DM / 128, NTOK / 128), 256>>>(p_xnorm, w_qkv, b_qkv, p_qkv, NTOK, 3 * DM, DM);
    // 3. gate = sigmoid(x @ w_gate + b_gate)
    gemm_kernel<true><<<dim3(DM / 128, NTOK / 128), 256>>>(x, w_gate, b_gate, p_gate, NTOK, DM, DM);
    // 4. gate /= rowmean+eps
    gate_norm_kernel<<<NTOK, 256>>>(p_gate);
    // 5. split into heads, apply gate + elu+1
    split_kernel<<<(NTOK * DM) / 256, 256>>>();
    // 6-8. chunked causal linear attention
    passA_kernel<<<NBH * NCH, 256>>>();
    passB_kernel<<<NBH, 256>>>();
    passC_kernel<<<NBH * NCH, 256, smemC>>>();
    // 9. projection
    gemm_kernel<false><<<dim3(DM / 128, NTOK / 128), 256>>>(p_ctx, w_proj, b_proj, out, NTOK, DM, DM);
}

// round 3
// speedup vs baseline: 2.1917x; 2.1917x over previous
#include <cuda_runtime.h>
#include <cuda_bf16.h>
#include <math.h>
#include <stdint.h>

// ---------------- problem constants ----------------
#define BATCH 2
#define SEQ   2048
#define DM    1024
#define NH    16
#define DH    64
#define NTOK  (BATCH*SEQ)        // 4096
#define CHUNK 128
#define NCH   (SEQ/CHUNK)        // 16
#define NBH   (BATCH*NH)         // 32

// ---------------- scratch (device globals; no allocs allowed) ----------------
__device__ float g_xnorm[NTOK*DM];
__device__ float g_qkv  [NTOK*3*DM];
__device__ float g_gate [NTOK*DM];
__device__ float g_qh   [NBH*SEQ*DH];
__device__ float g_kh   [NBH*SEQ*DH];
__device__ float g_vh   [NBH*SEQ*DH];
__device__ float g_kv   [NBH*NCH*DH*DH];
__device__ float g_kvpre[NBH*NCH*DH*DH];
__device__ float g_ksum [NBH*NCH*DH];
__device__ float g_kspre[NBH*NCH*DH];
__device__ float g_ctx  [NTOK*DM];

// ---------------- helpers ----------------
__device__ __forceinline__ float tf32r(float x) {
    float y; asm("cvt.rna.tf32.f32 %0, %1;" : "=f"(y) : "f"(x)); return y;
}
__device__ __forceinline__ void mma_tf32(float* c, const uint32_t* a, const uint32_t* b) {
    asm volatile(
        "mma.sync.aligned.m16n8k8.row.col.f32.tf32.tf32.f32 "
        "{%0,%1,%2,%3}, {%4,%5,%6,%7}, {%8,%9}, {%0,%1,%2,%3};"
        : "+f"(c[0]), "+f"(c[1]), "+f"(c[2]), "+f"(c[3])
        : "r"(a[0]), "r"(a[1]), "r"(a[2]), "r"(a[3]), "r"(b[0]), "r"(b[1]));
}

// ================= tf32 mma.sync GEMM =================
// D[M,N] = A[M,K] @ B[K,N] + bias ; optional sigmoid.
// Tile 128x128, BK=32, 256 threads (8 warps, 2x4), warp tile 64x32.
template<bool SIGMOID>
__global__ void __launch_bounds__(256)
mma_gemm(const float* __restrict__ A, const float* __restrict__ B,
         const float* __restrict__ bias, float* __restrict__ C,
         int M, int N, int K) {
    __shared__ float As[128][36];   // [m][k], pad 4
    __shared__ float Bs[32][136];   // [k][n], pad 8

    int tid = threadIdx.x;
    int wid = tid >> 5, lane = tid & 31;
    int gid = lane >> 2, tig = lane & 3;
    int wm = (wid & 1) * 64, wn = (wid >> 1) * 32;
    int bm0 = blockIdx.y * 128, bn0 = blockIdx.x * 128;

    float c[4][4][4];
    #pragma unroll
    for (int mf = 0; mf < 4; mf++)
        #pragma unroll
        for (int nf = 0; nf < 4; nf++)
            #pragma unroll
            for (int r = 0; r < 4; r++) c[mf][nf][r] = 0.f;

    for (int k0 = 0; k0 < K; k0 += 32) {
        // stage A: 128 rows x 32 k (8 float4/row), coalesced
        #pragma unroll
        for (int l = 0; l < 4; l++) {
            int id = tid + l * 256;              // 0..1023
            int m = id >> 3, kq = (id & 7) * 4;
            float4 av = *(const float4*)(A + (size_t)(bm0 + m) * K + k0 + kq);
            av.x = tf32r(av.x); av.y = tf32r(av.y); av.z = tf32r(av.z); av.w = tf32r(av.w);
            *(float4*)&As[m][kq] = av;
        }
        // stage B: 32 k-rows x 128 n, coalesced
        #pragma unroll
        for (int l = 0; l < 4; l++) {
            int id = tid + l * 256;              // 0..1023
            int kr = id >> 5, nc = (id & 31) * 4;
            float4 bv = *(const float4*)(B + (size_t)(k0 + kr) * N + bn0 + nc);
            bv.x = tf32r(bv.x); bv.y = tf32r(bv.y); bv.z = tf32r(bv.z); bv.w = tf32r(bv.w);
            *(float4*)&Bs[kr][nc] = bv;
        }
        __syncthreads();

        #pragma unroll
        for (int ks = 0; ks < 4; ks++) {
            int kb = ks * 8;
            uint32_t a[4][4], b[4][2];
            #pragma unroll
            for (int mf = 0; mf < 4; mf++) {
                int mr = wm + mf * 16 + gid;
                a[mf][0] = __float_as_uint(As[mr    ][kb + tig    ]);
                a[mf][1] = __float_as_uint(As[mr + 8][kb + tig    ]);
                a[mf][2] = __float_as_uint(As[mr    ][kb + tig + 4]);
                a[mf][3] = __float_as_uint(As[mr + 8][kb + tig + 4]);
            }
            #pragma unroll
            for (int nf = 0; nf < 4; nf++) {
                int nb = wn + nf * 8 + gid;
                b[nf][0] = __float_as_uint(Bs[kb + tig    ][nb]);
                b[nf][1] = __float_as_uint(Bs[kb + tig + 4][nb]);
            }
            #pragma unroll
            for (int mf = 0; mf < 4; mf++)
                #pragma unroll
                for (int nf = 0; nf < 4; nf++)
                    mma_tf32(c[mf][nf], a[mf], b[nf]);
        }
        __syncthreads();
    }

    // epilogue
    #pragma unroll
    for (int mf = 0; mf < 4; mf++) {
        int row = bm0 + wm + mf * 16 + gid;
        #pragma unroll
        for (int nf = 0; nf < 4; nf++) {
            int col = bn0 + wn + nf * 8 + tig * 2;
            float b0 = bias[col], b1 = bias[col + 1];
            float2 o0 = make_float2(c[mf][nf][0] + b0, c[mf][nf][1] + b1);
            float2 o1 = make_float2(c[mf][nf][2] + b0, c[mf][nf][3] + b1);
            if (SIGMOID) {
                o0.x = 1.f / (1.f + expf(-o0.x)); o0.y = 1.f / (1.f + expf(-o0.y));
                o1.x = 1.f / (1.f + expf(-o1.x)); o1.y = 1.f / (1.f + expf(-o1.y));
            }
            *(float2*)(C + (size_t)row * N + col) = o0;
            *(float2*)(C + (size_t)(row + 8) * N + col) = o1;
        }
    }
}

// ---------------- LayerNorm: one block per token row ----------------
__global__ void ln_kernel(const float* __restrict__ x, const float* __restrict__ g,
                          const float* __restrict__ bta, float* __restrict__ xn) {
    __shared__ float red0[8], red1[8];
    int row = blockIdx.x, tid = threadIdx.x;
    const float* xr = x + (size_t)row * DM;
    float4 xv = *(const float4*)(xr + tid * 4);
    float s  = xv.x + xv.y + xv.z + xv.w;
    float s2 = xv.x*xv.x + xv.y*xv.y + xv.z*xv.z + xv.w*xv.w;
    #pragma unroll
    for (int o = 16; o > 0; o >>= 1) {
        s  += __shfl_xor_sync(0xffffffffu, s,  o);
        s2 += __shfl_xor_sync(0xffffffffu, s2, o);
    }
    int w = tid >> 5;
    if ((tid & 31) == 0) { red0[w] = s; red1[w] = s2; }
    __syncthreads();
    if (tid < 32) {
        s  = (tid < 8) ? red0[tid] : 0.f;
        s2 = (tid < 8) ? red1[tid] : 0.f;
        #pragma unroll
        for (int o = 4; o > 0; o >>= 1) {
            s  += __shfl_xor_sync(0xffffffffu, s,  o);
            s2 += __shfl_xor_sync(0xffffffffu, s2, o);
        }
        if (tid == 0) { red0[0] = s; red1[0] = s2; }
    }
    __syncthreads();
    float mu   = red0[0] * (1.f / DM);
    float var  = red1[0] * (1.f / DM) - mu * mu;
    float rstd = rsqrtf(var + 1e-5f);
    float4 gv = *(const float4*)(g + tid * 4);
    float4 bv = *(const float4*)(bta + tid * 4);
    float4 o4;
    o4.x = (xv.x - mu) * rstd * gv.x + bv.x;
    o4.y = (xv.y - mu) * rstd * gv.y + bv.y;
    o4.z = (xv.z - mu) * rstd * gv.z + bv.z;
    o4.w = (xv.w - mu) * rstd * gv.w + bv.w;
    *(float4*)(xn + (size_t)row * DM + tid * 4) = o4;
}

// ---------------- gate normalize ----------------
__global__ void gate_norm_kernel(float* __restrict__ gate) {
    __shared__ float red[8];
    int row = blockIdx.x, tid = threadIdx.x;
    float* gr = gate + (size_t)row * DM;
    float4 gv = *(const float4*)(gr + tid * 4);
    float s = gv.x + gv.y + gv.z + gv.w;
    #pragma unroll
    for (int o = 16; o > 0; o >>= 1) s += __shfl_xor_sync(0xffffffffu, s, o);
    if ((tid & 31) == 0) red[tid >> 5] = s;
    __syncthreads();
    if (tid < 32) {
        s = (tid < 8) ? red[tid] : 0.f;
        #pragma unroll
        for (int o = 4; o > 0; o >>= 1) s += __shfl_xor_sync(0xffffffffu, s, o);
        if (tid == 0) red[0] = s;
    }
    __syncthreads();
    float scale = 1.f / (red[0] * (1.f / DM) + 1e-5f);
    gv.x *= scale; gv.y *= scale; gv.z *= scale; gv.w *= scale;
    *(float4*)(gr + tid * 4) = gv;
}

// ---------------- split qkv into head layout; gate + elu+1 ----------------
__global__ void split_kernel() {
    int idx = blockIdx.x * blockDim.x + threadIdx.x;
    if (idx >= NTOK * DM) return;
    int n = idx >> 10, cix = idx & 1023;
    int h = cix >> 6, e = cix & 63;
    int b = n >> 11, t = n & 2047;
    float gn = g_gate[idx];
    float qv = g_qkv[(size_t)n * 3072 + cix] * gn;
    float kv = g_qkv[(size_t)n * 3072 + 1024 + cix] * gn;
    float vv = g_qkv[(size_t)n * 3072 + 2048 + cix];
    qv = (qv > 0.f) ? qv + 1.f : expf(qv);
    kv = (kv > 0.f) ? kv + 1.f : expf(kv);
    int o = ((b * NH + h) * SEQ + t) * DH + e;
    g_qh[o] = qv; g_kh[o] = kv; g_vh[o] = vv;
}

// ---------------- pass A: per-chunk KV = k^T@v, ksum ----------------
__global__ void passA_kernel() {
    __shared__ float ks[64][64];
    __shared__ float vs[64][64];
    int blk = blockIdx.x;
    int bh = blk / NCH, c = blk % NCH;
    const float* kb = g_kh + ((size_t)bh * SEQ + c * CHUNK) * DH;
    const float* vb = g_vh + ((size_t)bh * SEQ + c * CHUNK) * DH;
    int tid = threadIdx.x;
    int d = tid & 63, mg = tid >> 6;
    float acc[16];
    #pragma unroll
    for (int i = 0; i < 16; i++) acc[i] = 0.f;
    float ksum = 0.f;
    for (int half = 0; half < 2; half++) {
        __syncthreads();
        #pragma unroll
        for (int l = 0; l < 4; l++) {
            int id = tid + l * 256;
            int r = id >> 4, c4 = (id & 15) * 4;
            *(float4*)&ks[r][c4] = *(const float4*)(kb + half * 64 * 64 + r * 64 + c4);
            *(float4*)&vs[r][c4] = *(const float4*)(vb + half * 64 * 64 + r * 64 + c4);
        }
        __syncthreads();
        #pragma unroll 4
        for (int t = 0; t < 64; t++) {
            float kd = ks[t][d];
            if (mg == 0) ksum += kd;
            #pragma unroll
            for (int i = 0; i < 16; i++) acc[i] += kd * vs[t][mg * 16 + i];
        }
    }
    float* kvo = g_kv + (size_t)blk * (DH * DH);
    #pragma unroll
    for (int i = 0; i < 16; i += 4)
        *(float4*)(kvo + d * 64 + mg * 16 + i) = make_float4(acc[i], acc[i+1], acc[i+2], acc[i+3]);
    if (mg == 0) g_ksum[blk * DH + d] = ksum;
}

// ---------------- pass B: exclusive prefix over chunks ----------------
__global__ void passB_kernel() {
    int bh = blockIdx.x;
    int tid = threadIdx.x;
    #pragma unroll
    for (int l = 0; l < 16; l++) {
        int e = tid + l * 256;
        float run = 0.f;
        for (int c = 0; c < NCH; c++) {
            size_t idx = ((size_t)bh * NCH + c) * (DH * DH) + e;
            g_kvpre[idx] = run;
            run += g_kv[idx];
        }
    }
    if (tid < DH) {
        float run = 0.f;
        for (int c = 0; c < NCH; c++) {
            size_t idx = ((size_t)bh * NCH + c) * DH + tid;
            g_kspre[idx] = run;
            run += g_ksum[idx];
        }
    }
}

// ---------------- pass C ----------------
__global__ void passC_kernel() {
    extern __shared__ float smf[];
    float (*k_sm)[64] = (float(*)[64])smf;
    float (*v_sm)[64] = (float(*)[64])(smf + 128 * 64);
    float (*s_sm)[64] = (float(*)[64])(smf + 2 * 128 * 64);
    float* kp_sm = smf + 2 * 128 * 64 + 64 * 64;

    int blk = blockIdx.x;
    int bh = blk / NCH, c = blk % NCH;
    int b = bh / NH, h = bh % NH;
    int tid = threadIdx.x;
    const float* qb = g_qh + ((size_t)bh * SEQ + c * CHUNK) * DH;
    const float* kb = g_kh + ((size_t)bh * SEQ + c * CHUNK) * DH;
    const float* vb = g_vh + ((size_t)bh * SEQ + c * CHUNK) * DH;

    #pragma unroll
    for (int l = 0; l < 8; l++) {
        int id = tid + l * 256;
        int r = id >> 4, c4 = (id & 15) * 4;
        *(float4*)&k_sm[r][c4] = *(const float4*)(kb + r * 64 + c4);
        *(float4*)&v_sm[r][c4] = *(const float4*)(vb + r * 64 + c4);
    }
    #pragma unroll
    for (int l = 0; l < 4; l++) {
        int id = tid + l * 256;
        int r = id >> 4, c4 = (id & 15) * 4;
        *(float4*)&s_sm[r][c4] = *(const float4*)(g_kvpre + (size_t)blk * 4096 + r * 64 + c4);
    }
    if (tid < 64) kp_sm[tid] = g_kspre[(size_t)blk * 64 + tid];
    __syncthreads();

    int t = tid >> 1, half = tid & 1;
    float q[64];
    #pragma unroll
    for (int i = 0; i < 64; i += 4) {
        float4 qv = *(const float4*)(qb + t * 64 + i);
        q[i] = qv.x; q[i+1] = qv.y; q[i+2] = qv.z; q[i+3] = qv.w;
    }
    float acc[32];
    #pragma unroll
    for (int i = 0; i < 32; i++) acc[i] = 0.f;
    float den = 0.f;

    #pragma unroll 8
    for (int d = 0; d < 64; d++) {
        float qd = q[d];
        den += qd * kp_sm[d];
        #pragma unroll
        for (int i = 0; i < 32; i++) acc[i] += qd * s_sm[d][half + 2 * i];
    }
    for (int s = 0; s <= t; s++) {
        float a = 0.f;
        #pragma unroll
        for (int d = 0; d < 64; d++) a += q[d] * k_sm[s][d];
        den += a;
        #pragma unroll
        for (int i = 0; i < 32; i++) acc[i] += a * v_sm[s][half + 2 * i];
    }
    float inv = 1.f / (den + 1e-5f);
    int token = b * SEQ + c * CHUNK + t;
    float* outp = g_ctx + (size_t)token * DM + h * DH;
    #pragma unroll
    for (int i = 0; i < 32; i++) outp[half + 2 * i] = acc[i] * inv;
}

// ---------------- launch ----------------
extern "C" void kernel_launch(void* const* d_in, const int* in_sizes, int n_in,
                              void* d_out, int out_size) {
    const float* x      = (const float*)d_in[0];
    const float* ln_g   = (const float*)d_in[1];
    const float* ln_b   = (const float*)d_in[2];
    const float* w_qkv  = (const float*)d_in[3];
    const float* b_qkv  = (const float*)d_in[4];
    const float* w_gate = (const float*)d_in[5];
    const float* b_gate = (const float*)d_in[6];
    const float* w_proj = (const float*)d_in[7];
    const float* b_proj = (const float*)d_in[8];
    float* out = (float*)d_out;

    float *p_xnorm, *p_qkv, *p_gate, *p_ctx;
    cudaGetSymbolAddress((void**)&p_xnorm, g_xnorm);
    cudaGetSymbolAddress((void**)&p_qkv,   g_qkv);
    cudaGetSymbolAddress((void**)&p_gate,  g_gate);
    cudaGetSymbolAddress((void**)&p_ctx,   g_ctx);

    const int smemC = (2 * 128 * 64 + 64 * 64 + 64) * 4;
    cudaFuncSetAttribute(passC_kernel, cudaFuncAttributeMaxDynamicSharedMemorySize, smemC);

    // 1. LayerNorm
    ln_kernel<<<NTOK, 256>>>(x, ln_g, ln_b, p_xnorm);
    // 2. qkv = xnorm @ w_qkv + b_qkv  (tf32 mma.sync)
    mma_gemm<false><<<dim3(3 * DM / 128, NTOK / 128), 256>>>(p_xnorm, w_qkv, b_qkv, p_qkv, NTOK, 3 * DM, DM);
    // 3. gate = sigmoid(x @ w_gate + b_gate)
    mma_gemm<true><<<dim3(DM / 128, NTOK / 128), 256>>>(x, w_gate, b_gate, p_gate, NTOK, DM, DM);
    // 4. gate /= rowmean+eps
    gate_norm_kernel<<<NTOK, 256>>>(p_gate);
    // 5. split into heads, apply gate + elu+1
    split_kernel<<<(NTOK * DM) / 256, 256>>>();
    // 6-8. chunked causal linear attention
    passA_kernel<<<NBH * NCH, 256>>>();
    passB_kernel<<<NBH, 256>>>();
    passC_kernel<<<NBH * NCH, 256, smemC>>>();
    // 9. projection
    mma_gemm<false><<<dim3(DM / 128, NTOK / 128), 256>>>(p_ctx, w_proj, b_proj, out, NTOK, DM, DM);
}

// round 4
// speedup vs baseline: 2.4287x; 1.1081x over previous
#include <cuda_runtime.h>
#include <cuda_bf16.h>
#include <math.h>
#include <stdint.h>

// ---------------- problem constants ----------------
#define BATCH 2
#define SEQ   2048
#define DM    1024
#define NH    16
#define DH    64
#define NTOK  (BATCH*SEQ)        // 4096
#define CHUNK 128
#define NCH   (SEQ/CHUNK)        // 16
#define NBH   (BATCH*NH)         // 32

// ---------------- scratch (device globals; no allocs allowed) ----------------
__device__ float g_xnorm[NTOK*DM];
__device__ float g_xr   [NTOK*DM];
__device__ float g_qkv  [NTOK*3*DM];
__device__ float g_gate [NTOK*DM];
__device__ float g_qh   [NBH*SEQ*DH];
__device__ float g_kh   [NBH*SEQ*DH];
__device__ float g_vh   [NBH*SEQ*DH];
__device__ float g_kv   [NBH*NCH*DH*DH];
__device__ float g_kvpre[NBH*NCH*DH*DH];
__device__ float g_ksum [NBH*NCH*DH];
__device__ float g_kspre[NBH*NCH*DH];
__device__ float g_ctx  [NTOK*DM];
__device__ float g_wqkv [3*DM*DM];
__device__ float g_wgate[DM*DM];
__device__ float g_wproj[DM*DM];

// ---------------- helpers ----------------
__device__ __forceinline__ float tf32r(float x) {
    float y; asm("cvt.rna.tf32.f32 %0, %1;" : "=f"(y) : "f"(x)); return y;
}
__device__ __forceinline__ void mma_tf32(float* c, const uint32_t* a, const uint32_t* b) {
    asm volatile(
        "mma.sync.aligned.m16n8k8.row.col.f32.tf32.tf32.f32 "
        "{%0,%1,%2,%3}, {%4,%5,%6,%7}, {%8,%9}, {%0,%1,%2,%3};"
        : "+f"(c[0]), "+f"(c[1]), "+f"(c[2]), "+f"(c[3])
        : "r"(a[0]), "r"(a[1]), "r"(a[2]), "r"(a[3]), "r"(b[0]), "r"(b[1]));
}
__device__ __forceinline__ uint32_t smem_u32(const void* p) {
    uint32_t a;
    asm("{ .reg .u64 t; cvta.to.shared.u64 t, %1; cvt.u32.u64 %0, t; }" : "=r"(a) : "l"(p));
    return a;
}
__device__ __forceinline__ void cp16(uint32_t dst, const void* src) {
    asm volatile("cp.async.cg.shared.global [%0], [%1], 16;" :: "r"(dst), "l"(src));
}
#define CP_COMMIT() asm volatile("cp.async.commit_group;" ::: "memory")
#define CP_WAIT1()  asm volatile("cp.async.wait_group 1;" ::: "memory")

// ================= tf32 mma.sync GEMM (cp.async double-buffered) =================
// D[M,N] = A[M,K] @ B[K,N] + bias ; optional sigmoid. A,B pre-rounded to tf32.
// Tile 128x128, BK=32, 256 threads (8 warps, 2x4), warp tile 64x32.
// smem layout (floats): A stage s at s*4608 (128x36), B stage s at 9216 + s*4352 (32x136)
#define GEMM_SMEM_BYTES (2*(128*36 + 32*136)*4)

template<bool SIGMOID>
__global__ void __launch_bounds__(256)
mma_gemm(const float* __restrict__ A, const float* __restrict__ B,
         const float* __restrict__ bias, float* __restrict__ C,
         int M, int N, int K) {
    extern __shared__ float smf[];
    uint32_t sA = smem_u32(smf);            // bytes
    uint32_t sB = sA + 2 * 128 * 36 * 4;

    int tid = threadIdx.x;
    int wid = tid >> 5, lane = tid & 31;
    int gid = lane >> 2, tig = lane & 3;
    int wm = (wid & 1) * 64, wn = (wid >> 1) * 32;
    int bm0 = blockIdx.y * 128, bn0 = blockIdx.x * 128;

    // per-thread staging coords
    int am = tid >> 1, akq = (tid & 1) * 16;          // A: 2 thr/row, 16 floats apart -> 4 rows per l? no:
    // simpler: reuse id-based mapping inside loop

    float c[4][4][4];
    #pragma unroll
    for (int mf = 0; mf < 4; mf++)
        #pragma unroll
        for (int nf = 0; nf < 4; nf++)
            #pragma unroll
            for (int r = 0; r < 4; r++) c[mf][nf][r] = 0.f;

    const int NKT = K / 32;

    // ---- stage tile kt into buffer s ----
    auto stage = [&](int s, int kt) {
        const float* Ab = A + (size_t)bm0 * K + kt * 32;
        const float* Bb = B + (size_t)(kt * 32) * N + bn0;
        uint32_t sAb = sA + s * (128 * 36 * 4);
        uint32_t sBb = sB + s * (32 * 136 * 4);
        #pragma unroll
        for (int l = 0; l < 4; l++) {
            int id = tid + l * 256;                  // 0..1023
            int m = id >> 3, kq = (id & 7) * 4;      // A: 128 x 32
            cp16(sAb + (m * 36 + kq) * 4, Ab + (size_t)m * K + kq);
            int kr = id >> 5, nc = (id & 31) * 4;    // B: 32 x 128
            cp16(sBb + (kr * 136 + nc) * 4, Bb + (size_t)kr * N + nc);
        }
    };

    stage(0, 0);
    CP_COMMIT();

    for (int kt = 0; kt < NKT; kt++) {
        int buf = kt & 1;
        if (kt + 1 < NKT) stage(buf ^ 1, kt + 1);
        CP_COMMIT();
        CP_WAIT1();                                  // tile kt resident
        __syncthreads();

        const float* As_ = smf + buf * (128 * 36);
        const float* Bs_ = smf + 2 * 128 * 36 + buf * (32 * 136);
        #pragma unroll
        for (int ks = 0; ks < 4; ks++) {
            int kb = ks * 8;
            uint32_t a[4][4], b[4][2];
            #pragma unroll
            for (int mf = 0; mf < 4; mf++) {
                int mr = wm + mf * 16 + gid;
                a[mf][0] = __float_as_uint(As_[(mr    ) * 36 + kb + tig    ]);
                a[mf][1] = __float_as_uint(As_[(mr + 8) * 36 + kb + tig    ]);
                a[mf][2] = __float_as_uint(As_[(mr    ) * 36 + kb + tig + 4]);
                a[mf][3] = __float_as_uint(As_[(mr + 8) * 36 + kb + tig + 4]);
            }
            #pragma unroll
            for (int nf = 0; nf < 4; nf++) {
                int nb = wn + nf * 8 + gid;
                b[nf][0] = __float_as_uint(Bs_[(kb + tig    ) * 136 + nb]);
                b[nf][1] = __float_as_uint(Bs_[(kb + tig + 4) * 136 + nb]);
            }
            #pragma unroll
            for (int mf = 0; mf < 4; mf++)
                #pragma unroll
                for (int nf = 0; nf < 4; nf++)
                    mma_tf32(c[mf][nf], a[mf], b[nf]);
        }
        __syncthreads();
    }

    // epilogue
    #pragma unroll
    for (int mf = 0; mf < 4; mf++) {
        int row = bm0 + wm + mf * 16 + gid;
        #pragma unroll
        for (int nf = 0; nf < 4; nf++) {
            int col = bn0 + wn + nf * 8 + tig * 2;
            float b0 = bias[col], b1 = bias[col + 1];
            float2 o0 = make_float2(c[mf][nf][0] + b0, c[mf][nf][1] + b1);
            float2 o1 = make_float2(c[mf][nf][2] + b0, c[mf][nf][3] + b1);
            if (SIGMOID) {
                o0.x = 1.f / (1.f + expf(-o0.x)); o0.y = 1.f / (1.f + expf(-o0.y));
                o1.x = 1.f / (1.f + expf(-o1.x)); o1.y = 1.f / (1.f + expf(-o1.y));
            }
            *(float2*)(C + (size_t)row * N + col) = o0;
            *(float2*)(C + (size_t)(row + 8) * N + col) = o1;
        }
    }
}

// ---------------- round fp32 -> tf32 copy ----------------
__global__ void round_kernel(const float* __restrict__ src, float* __restrict__ dst) {
    int i = blockIdx.x * blockDim.x + threadIdx.x;
    float4 v = ((const float4*)src)[i];
    v.x = tf32r(v.x); v.y = tf32r(v.y); v.z = tf32r(v.z); v.w = tf32r(v.w);
    ((float4*)dst)[i] = v;
}

// ---------------- LayerNorm: rounded xnorm + rounded x copy ----------------
__global__ void ln_kernel(const float* __restrict__ x, const float* __restrict__ g,
                          const float* __restrict__ bta, float* __restrict__ xn,
                          float* __restrict__ xr) {
    __shared__ float red0[8], red1[8];
    int row = blockIdx.x, tid = threadIdx.x;
    const float* xrp = x + (size_t)row * DM;
    float4 xv = *(const float4*)(xrp + tid * 4);
    float s  = xv.x + xv.y + xv.z + xv.w;
    float s2 = xv.x*xv.x + xv.y*xv.y + xv.z*xv.z + xv.w*xv.w;
    #pragma unroll
    for (int o = 16; o > 0; o >>= 1) {
        s  += __shfl_xor_sync(0xffffffffu, s,  o);
        s2 += __shfl_xor_sync(0xffffffffu, s2, o);
    }
    int w = tid >> 5;
    if ((tid & 31) == 0) { red0[w] = s; red1[w] = s2; }
    __syncthreads();
    if (tid < 32) {
        s  = (tid < 8) ? red0[tid] : 0.f;
        s2 = (tid < 8) ? red1[tid] : 0.f;
        #pragma unroll
        for (int o = 4; o > 0; o >>= 1) {
            s  += __shfl_xor_sync(0xffffffffu, s,  o);
            s2 += __shfl_xor_sync(0xffffffffu, s2, o);
        }
        if (tid == 0) { red0[0] = s; red1[0] = s2; }
    }
    __syncthreads();
    float mu   = red0[0] * (1.f / DM);
    float var  = red1[0] * (1.f / DM) - mu * mu;
    float rstd = rsqrtf(var + 1e-5f);
    float4 gv = *(const float4*)(g + tid * 4);
    float4 bv = *(const float4*)(bta + tid * 4);
    float4 o4;
    o4.x = tf32r((xv.x - mu) * rstd * gv.x + bv.x);
    o4.y = tf32r((xv.y - mu) * rstd * gv.y + bv.y);
    o4.z = tf32r((xv.z - mu) * rstd * gv.z + bv.z);
    o4.w = tf32r((xv.w - mu) * rstd * gv.w + bv.w);
    *(float4*)(xn + (size_t)row * DM + tid * 4) = o4;
    float4 r4;
    r4.x = tf32r(xv.x); r4.y = tf32r(xv.y); r4.z = tf32r(xv.z); r4.w = tf32r(xv.w);
    *(float4*)(xr + (size_t)row * DM + tid * 4) = r4;
}

// ---------------- fused gate-normalize + head split + elu+1 ----------------
__global__ void gatesplit_kernel() {
    __shared__ float red[8];
    int n = blockIdx.x, tid = threadIdx.x;      // one token per block
    float4 gv = *(const float4*)(g_gate + (size_t)n * DM + tid * 4);
    float s = gv.x + gv.y + gv.z + gv.w;
    #pragma unroll
    for (int o = 16; o > 0; o >>= 1) s += __shfl_xor_sync(0xffffffffu, s, o);
    if ((tid & 31) == 0) red[tid >> 5] = s;
    __syncthreads();
    if (tid < 32) {
        s = (tid < 8) ? red[tid] : 0.f;
        #pragma unroll
        for (int o = 4; o > 0; o >>= 1) s += __shfl_xor_sync(0xffffffffu, s, o);
        if (tid == 0) red[0] = s;
    }
    __syncthreads();
    float scale = 1.f / (red[0] * (1.f / DM) + 1e-5f);

    int cix = tid * 4;
    int h = cix >> 6, e = cix & 63;
    int b = n >> 11, t = n & 2047;
    const float* qkv = g_qkv + (size_t)n * 3072;
    float4 q4 = *(const float4*)(qkv + cix);
    float4 k4 = *(const float4*)(qkv + 1024 + cix);
    float4 v4 = *(const float4*)(qkv + 2048 + cix);
    float gn0 = gv.x * scale, gn1 = gv.y * scale, gn2 = gv.z * scale, gn3 = gv.w * scale;
    q4.x *= gn0; q4.y *= gn1; q4.z *= gn2; q4.w *= gn3;
    k4.x *= gn0; k4.y *= gn1; k4.z *= gn2; k4.w *= gn3;
    q4.x = (q4.x > 0.f) ? q4.x + 1.f : expf(q4.x);
    q4.y = (q4.y > 0.f) ? q4.y + 1.f : expf(q4.y);
    q4.z = (q4.z > 0.f) ? q4.z + 1.f : expf(q4.z);
    q4.w = (q4.w > 0.f) ? q4.w + 1.f : expf(q4.w);
    k4.x = (k4.x > 0.f) ? k4.x + 1.f : expf(k4.x);
    k4.y = (k4.y > 0.f) ? k4.y + 1.f : expf(k4.y);
    k4.z = (k4.z > 0.f) ? k4.z + 1.f : expf(k4.z);
    k4.w = (k4.w > 0.f) ? k4.w + 1.f : expf(k4.w);
    size_t o = ((size_t)(b * NH + h) * SEQ + t) * DH + e;
    *(float4*)(g_qh + o) = q4;
    *(float4*)(g_kh + o) = k4;
    *(float4*)(g_vh + o) = v4;
}

// ---------------- pass A: per-chunk KV = k^T@v, ksum ----------------
__global__ void passA_kernel() {
    __shared__ float ks[64][64];
    __shared__ float vs[64][64];
    int blk = blockIdx.x;
    int bh = blk / NCH, c = blk % NCH;
    const float* kb = g_kh + ((size_t)bh * SEQ + c * CHUNK) * DH;
    const float* vb = g_vh + ((size_t)bh * SEQ + c * CHUNK) * DH;
    int tid = threadIdx.x;
    int d = tid & 63, mg = tid >> 6;
    float acc[16];
    #pragma unroll
    for (int i = 0; i < 16; i++) acc[i] = 0.f;
    float ksum = 0.f;
    for (int half = 0; half < 2; half++) {
        __syncthreads();
        #pragma unroll
        for (int l = 0; l < 4; l++) {
            int id = tid + l * 256;
            int r = id >> 4, c4 = (id & 15) * 4;
            *(float4*)&ks[r][c4] = *(const float4*)(kb + half * 64 * 64 + r * 64 + c4);
            *(float4*)&vs[r][c4] = *(const float4*)(vb + half * 64 * 64 + r * 64 + c4);
        }
        __syncthreads();
        #pragma unroll 4
        for (int t = 0; t < 64; t++) {
            float kd = ks[t][d];
            if (mg == 0) ksum += kd;
            #pragma unroll
            for (int i = 0; i < 16; i++) acc[i] += kd * vs[t][mg * 16 + i];
        }
    }
    float* kvo = g_kv + (size_t)blk * (DH * DH);
    #pragma unroll
    for (int i = 0; i < 16; i += 4)
        *(float4*)(kvo + d * 64 + mg * 16 + i) = make_float4(acc[i], acc[i+1], acc[i+2], acc[i+3]);
    if (mg == 0) g_ksum[blk * DH + d] = ksum;
}

// ---------------- pass B: exclusive prefix over chunks (512 blocks) ----------------
__global__ void passB_kernel() {
    int bh = blockIdx.y;
    int e = blockIdx.x * 256 + threadIdx.x;     // 16 x 256 = 4096 elems
    float run = 0.f;
    #pragma unroll
    for (int c = 0; c < NCH; c++) {
        size_t idx = ((size_t)bh * NCH + c) * (DH * DH) + e;
        g_kvpre[idx] = run;
        run += g_kv[idx];
    }
    if (blockIdx.x == 0 && threadIdx.x < DH) {
        float r2 = 0.f;
        #pragma unroll
        for (int c = 0; c < NCH; c++) {
            size_t idx = ((size_t)bh * NCH + c) * DH + threadIdx.x;
            g_kspre[idx] = r2;
            r2 += g_ksum[idx];
        }
    }
}

// ---------------- pass C (output rounded to tf32 for proj GEMM) ----------------
__global__ void passC_kernel() {
    extern __shared__ float smf[];
    float (*k_sm)[64] = (float(*)[64])smf;
    float (*v_sm)[64] = (float(*)[64])(smf + 128 * 64);
    float (*s_sm)[64] = (float(*)[64])(smf + 2 * 128 * 64);
    float* kp_sm = smf + 2 * 128 * 64 + 64 * 64;

    int blk = blockIdx.x;
    int bh = blk / NCH, c = blk % NCH;
    int b = bh / NH, h = bh % NH;
    int tid = threadIdx.x;
    const float* qb = g_qh + ((size_t)bh * SEQ + c * CHUNK) * DH;
    const float* kb = g_kh + ((size_t)bh * SEQ + c * CHUNK) * DH;
    const float* vb = g_vh + ((size_t)bh * SEQ + c * CHUNK) * DH;

    #pragma unroll
    for (int l = 0; l < 8; l++) {
        int id = tid + l * 256;
        int r = id >> 4, c4 = (id & 15) * 4;
        *(float4*)&k_sm[r][c4] = *(const float4*)(kb + r * 64 + c4);
        *(float4*)&v_sm[r][c4] = *(const float4*)(vb + r * 64 + c4);
    }
    #pragma unroll
    for (int l = 0; l < 4; l++) {
        int id = tid + l * 256;
        int r = id >> 4, c4 = (id & 15) * 4;
        *(float4*)&s_sm[r][c4] = *(const float4*)(g_kvpre + (size_t)blk * 4096 + r * 64 + c4);
    }
    if (tid < 64) kp_sm[tid] = g_kspre[(size_t)blk * 64 + tid];
    __syncthreads();

    int t = tid >> 1, half = tid & 1;
    float q[64];
    #pragma unroll
    for (int i = 0; i < 64; i += 4) {
        float4 qv = *(const float4*)(qb + t * 64 + i);
        q[i] = qv.x; q[i+1] = qv.y; q[i+2] = qv.z; q[i+3] = qv.w;
    }
    float acc[32];
    #pragma unroll
    for (int i = 0; i < 32; i++) acc[i] = 0.f;
    float den = 0.f;

    #pragma unroll 8
    for (int d = 0; d < 64; d++) {
        float qd = q[d];
        den += qd * kp_sm[d];
        #pragma unroll
        for (int i = 0; i < 32; i++) acc[i] += qd * s_sm[d][half + 2 * i];
    }
    for (int s = 0; s <= t; s++) {
        float a = 0.f;
        #pragma unroll
        for (int d = 0; d < 64; d++) a += q[d] * k_sm[s][d];
        den += a;
        #pragma unroll
        for (int i = 0; i < 32; i++) acc[i] += a * v_sm[s][half + 2 * i];
    }
    float inv = 1.f / (den + 1e-5f);
    int token = b * SEQ + c * CHUNK + t;
    float* outp = g_ctx + (size_t)token * DM + h * DH;
    #pragma unroll
    for (int i = 0; i < 32; i++) outp[half + 2 * i] = tf32r(acc[i] * inv);
}

// ---------------- launch ----------------
extern "C" void kernel_launch(void* const* d_in, const int* in_sizes, int n_in,
                              void* d_out, int out_size) {
    const float* x      = (const float*)d_in[0];
    const float* ln_g   = (const float*)d_in[1];
    const float* ln_b   = (const float*)d_in[2];
    const float* w_qkv  = (const float*)d_in[3];
    const float* b_qkv  = (const float*)d_in[4];
    const float* w_gate = (const float*)d_in[5];
    const float* b_gate = (const float*)d_in[6];
    const float* w_proj = (const float*)d_in[7];
    const float* b_proj = (const float*)d_in[8];
    float* out = (float*)d_out;

    float *p_xnorm, *p_xr, *p_qkv, *p_gate, *p_ctx, *p_wqkv, *p_wgate, *p_wproj;
    cudaGetSymbolAddress((void**)&p_xnorm, g_xnorm);
    cudaGetSymbolAddress((void**)&p_xr,    g_xr);
    cudaGetSymbolAddress((void**)&p_qkv,   g_qkv);
    cudaGetSymbolAddress((void**)&p_gate,  g_gate);
    cudaGetSymbolAddress((void**)&p_ctx,   g_ctx);
    cudaGetSymbolAddress((void**)&p_wqkv,  g_wqkv);
    cudaGetSymbolAddress((void**)&p_wgate, g_wgate);
    cudaGetSymbolAddress((void**)&p_wproj, g_wproj);

    const int smemC = (2 * 128 * 64 + 64 * 64 + 64) * 4;
    cudaFuncSetAttribute(passC_kernel, cudaFuncAttributeMaxDynamicSharedMemorySize, smemC);
    cudaFuncSetAttribute(mma_gemm<false>, cudaFuncAttributeMaxDynamicSharedMemorySize, GEMM_SMEM_BYTES);
    cudaFuncSetAttribute(mma_gemm<true>,  cudaFuncAttributeMaxDynamicSharedMemorySize, GEMM_SMEM_BYTES);

    // 0. round weights to tf32 copies
    round_kernel<<<(3 * DM * DM / 4) / 256, 256>>>(w_qkv, p_wqkv);
    round_kernel<<<(DM * DM / 4) / 256, 256>>>(w_gate, p_wgate);
    round_kernel<<<(DM * DM / 4) / 256, 256>>>(w_proj, p_wproj);
    // 1. LayerNorm (emits rounded xnorm + rounded x)
    ln_kernel<<<NTOK, 256>>>(x, ln_g, ln_b, p_xnorm, p_xr);
    // 2. qkv = xnorm @ w_qkv + b_qkv
    mma_gemm<false><<<dim3(3 * DM / 128, NTOK / 128), 256, GEMM_SMEM_BYTES>>>(p_xnorm, p_wqkv, b_qkv, p_qkv, NTOK, 3 * DM, DM);
    // 3. gate = sigmoid(x @ w_gate + b_gate)
    mma_gemm<true><<<dim3(DM / 128, NTOK / 128), 256, GEMM_SMEM_BYTES>>>(p_xr, p_wgate, b_gate, p_gate, NTOK, DM, DM);
    // 4+5. fused gate-normalize + split + elu+1
    gatesplit_kernel<<<NTOK, 256>>>();
    // 6-8. chunked causal linear attention
    passA_kernel<<<NBH * NCH, 256>>>();
    passB_kernel<<<dim3(16, NBH), 256>>>();
    passC_kernel<<<NBH * NCH, 256, smemC>>>();
    // 9. projection
    mma_gemm<false><<<dim3(DM / 128, NTOK / 128), 256, GEMM_SMEM_BYTES>>>(p_ctx, p_wproj, b_proj, out, NTOK, DM, DM);
}

// round 5
// speedup vs baseline: 2.6635x; 1.0967x over previous
#include <cuda_runtime.h>
#include <cuda_bf16.h>
#include <math.h>
#include <stdint.h>

// ---------------- problem constants ----------------
#define BATCH 2
#define SEQ   2048
#define DM    1024
#define NH    16
#define DH    64
#define NTOK  (BATCH*SEQ)        // 4096
#define CHUNK 128
#define NCH   (SEQ/CHUNK)        // 16
#define NBH   (BATCH*NH)         // 32

// ---------------- scratch (device globals; no allocs allowed) ----------------
__device__ float g_xnorm[NTOK*DM];
__device__ float g_xr   [NTOK*DM];
__device__ float g_qkv  [NTOK*3*DM];
__device__ float g_gate [NTOK*DM];
__device__ float g_qh   [NBH*SEQ*DH];
__device__ float g_kh   [NBH*SEQ*DH];
__device__ float g_vh   [NBH*SEQ*DH];
__device__ float g_kv   [NBH*NCH*DH*DH];
__device__ float g_kvpre[NBH*NCH*DH*DH];
__device__ float g_ksum [NBH*NCH*DH];
__device__ float g_kspre[NBH*NCH*DH];
__device__ float g_ctx  [NTOK*DM];
__device__ float g_wqkv [3*DM*DM];
__device__ float g_wgate[DM*DM];
__device__ float g_wproj[DM*DM];

// ---------------- helpers ----------------
__device__ __forceinline__ float tf32r(float x) {
    float y; asm("cvt.rna.tf32.f32 %0, %1;" : "=f"(y) : "f"(x)); return y;
}
__device__ __forceinline__ void mma_tf32(float* c, const uint32_t* a, const uint32_t* b) {
    asm volatile(
        "mma.sync.aligned.m16n8k8.row.col.f32.tf32.tf32.f32 "
        "{%0,%1,%2,%3}, {%4,%5,%6,%7}, {%8,%9}, {%0,%1,%2,%3};"
        : "+f"(c[0]), "+f"(c[1]), "+f"(c[2]), "+f"(c[3])
        : "r"(a[0]), "r"(a[1]), "r"(a[2]), "r"(a[3]), "r"(b[0]), "r"(b[1]));
}
__device__ __forceinline__ uint32_t smem_u32(const void* p) {
    uint32_t a;
    asm("{ .reg .u64 t; cvta.to.shared.u64 t, %1; cvt.u32.u64 %0, t; }" : "=r"(a) : "l"(p));
    return a;
}
__device__ __forceinline__ void cp16(uint32_t dst, const void* src) {
    asm volatile("cp.async.cg.shared.global [%0], [%1], 16;" :: "r"(dst), "l"(src));
}
#define CP_COMMIT() asm volatile("cp.async.commit_group;" ::: "memory")
#define CP_WAIT(n)  asm volatile("cp.async.wait_group %0;" :: "n"(n) : "memory")

// ================= tf32 mma.sync GEMM, 3-stage cp.async =================
// D[M,N] = A[M,K] @ B[K,N] + bias ; optional sigmoid. A,B pre-rounded to tf32.
// CTA tile 128x128, BK=32, 128 threads (4 warps 2x2), warp tile 64x64.
#define AST (128*36)             // A stage floats
#define BST (32*136)             // B stage floats
#define GEMM_SMEM_BYTES (3*(AST+BST)*4)   // 107520

template<bool SIGMOID>
__global__ void __launch_bounds__(128)
mma_gemm(const float* __restrict__ A, const float* __restrict__ B,
         const float* __restrict__ bias, float* __restrict__ C,
         int M, int N, int K) {
    extern __shared__ float smf[];
    uint32_t sA = smem_u32(smf);
    uint32_t sB = sA + 3 * AST * 4;

    int tid = threadIdx.x;
    int wid = tid >> 5, lane = tid & 31;
    int gid = lane >> 2, tig = lane & 3;
    int wm = (wid & 1) * 64, wn = (wid >> 1) * 64;
    int bm0 = blockIdx.y * 128, bn0 = blockIdx.x * 128;

    float c[4][8][4];
    #pragma unroll
    for (int mf = 0; mf < 4; mf++)
        #pragma unroll
        for (int nf = 0; nf < 8; nf++)
            #pragma unroll
            for (int r = 0; r < 4; r++) c[mf][nf][r] = 0.f;

    const int NKT = K / 32;

    auto stage = [&](int s, int kt) {
        const float* Ab = A + (size_t)bm0 * K + kt * 32;
        const float* Bb = B + (size_t)(kt * 32) * N + bn0;
        uint32_t sAb = sA + s * (AST * 4);
        uint32_t sBb = sB + s * (BST * 4);
        #pragma unroll
        for (int l = 0; l < 8; l++) {
            int id = tid + l * 128;                  // 0..1023
            int m = id >> 3, kq = (id & 7) * 4;      // A: 128 x 32
            cp16(sAb + (m * 36 + kq) * 4, Ab + (size_t)m * K + kq);
            int kr = id >> 5, nc = (id & 31) * 4;    // B: 32 x 128
            cp16(sBb + (kr * 136 + nc) * 4, Bb + (size_t)kr * N + nc);
        }
    };

    stage(0, 0); CP_COMMIT();
    stage(1, 1); CP_COMMIT();

    for (int kt = 0; kt < NKT; kt++) {
        if (kt + 1 < NKT) { CP_WAIT(1); } else { CP_WAIT(0); }
        __syncthreads();

        int buf = kt % 3;
        const float* As_ = smf + buf * AST;
        const float* Bs_ = smf + 3 * AST + buf * BST;
        #pragma unroll
        for (int ks = 0; ks < 4; ks++) {
            int kb = ks * 8;
            uint32_t a[4][4], b[8][2];
            #pragma unroll
            for (int mf = 0; mf < 4; mf++) {
                int mr = wm + mf * 16 + gid;
                a[mf][0] = __float_as_uint(As_[(mr    ) * 36 + kb + tig    ]);
                a[mf][1] = __float_as_uint(As_[(mr + 8) * 36 + kb + tig    ]);
                a[mf][2] = __float_as_uint(As_[(mr    ) * 36 + kb + tig + 4]);
                a[mf][3] = __float_as_uint(As_[(mr + 8) * 36 + kb + tig + 4]);
            }
            #pragma unroll
            for (int nf = 0; nf < 8; nf++) {
                int nb = wn + nf * 8 + gid;
                b[nf][0] = __float_as_uint(Bs_[(kb + tig    ) * 136 + nb]);
                b[nf][1] = __float_as_uint(Bs_[(kb + tig + 4) * 136 + nb]);
            }
            #pragma unroll
            for (int mf = 0; mf < 4; mf++)
                #pragma unroll
                for (int nf = 0; nf < 8; nf++)
                    mma_tf32(c[mf][nf], a[mf], b[nf]);
        }

        if (kt + 2 < NKT) { stage((kt + 2) % 3, kt + 2); CP_COMMIT(); }
    }

    // epilogue
    #pragma unroll
    for (int mf = 0; mf < 4; mf++) {
        int row = bm0 + wm + mf * 16 + gid;
        #pragma unroll
        for (int nf = 0; nf < 8; nf++) {
            int col = bn0 + wn + nf * 8 + tig * 2;
            float b0 = bias[col], b1 = bias[col + 1];
            float2 o0 = make_float2(c[mf][nf][0] + b0, c[mf][nf][1] + b1);
            float2 o1 = make_float2(c[mf][nf][2] + b0, c[mf][nf][3] + b1);
            if (SIGMOID) {
                o0.x = 1.f / (1.f + expf(-o0.x)); o0.y = 1.f / (1.f + expf(-o0.y));
                o1.x = 1.f / (1.f + expf(-o1.x)); o1.y = 1.f / (1.f + expf(-o1.y));
            }
            *(float2*)(C + (size_t)row * N + col) = o0;
            *(float2*)(C + (size_t)(row + 8) * N + col) = o1;
        }
    }
}

// ---------------- round fp32 -> tf32 copy ----------------
__global__ void round_kernel(const float* __restrict__ src, float* __restrict__ dst) {
    int i = blockIdx.x * blockDim.x + threadIdx.x;
    float4 v = ((const float4*)src)[i];
    v.x = tf32r(v.x); v.y = tf32r(v.y); v.z = tf32r(v.z); v.w = tf32r(v.w);
    ((float4*)dst)[i] = v;
}

// ---------------- LayerNorm: rounded xnorm + rounded x copy ----------------
__global__ void ln_kernel(const float* __restrict__ x, const float* __restrict__ g,
                          const float* __restrict__ bta, float* __restrict__ xn,
                          float* __restrict__ xr) {
    __shared__ float red0[8], red1[8];
    int row = blockIdx.x, tid = threadIdx.x;
    const float* xrp = x + (size_t)row * DM;
    float4 xv = *(const float4*)(xrp + tid * 4);
    float s  = xv.x + xv.y + xv.z + xv.w;
    float s2 = xv.x*xv.x + xv.y*xv.y + xv.z*xv.z + xv.w*xv.w;
    #pragma unroll
    for (int o = 16; o > 0; o >>= 1) {
        s  += __shfl_xor_sync(0xffffffffu, s,  o);
        s2 += __shfl_xor_sync(0xffffffffu, s2, o);
    }
    int w = tid >> 5;
    if ((tid & 31) == 0) { red0[w] = s; red1[w] = s2; }
    __syncthreads();
    if (tid < 32) {
        s  = (tid < 8) ? red0[tid] : 0.f;
        s2 = (tid < 8) ? red1[tid] : 0.f;
        #pragma unroll
        for (int o = 4; o > 0; o >>= 1) {
            s  += __shfl_xor_sync(0xffffffffu, s,  o);
            s2 += __shfl_xor_sync(0xffffffffu, s2, o);
        }
        if (tid == 0) { red0[0] = s; red1[0] = s2; }
    }
    __syncthreads();
    float mu   = red0[0] * (1.f / DM);
    float var  = red1[0] * (1.f / DM) - mu * mu;
    float rstd = rsqrtf(var + 1e-5f);
    float4 gv = *(const float4*)(g + tid * 4);
    float4 bv = *(const float4*)(bta + tid * 4);
    float4 o4;
    o4.x = tf32r((xv.x - mu) * rstd * gv.x + bv.x);
    o4.y = tf32r((xv.y - mu) * rstd * gv.y + bv.y);
    o4.z = tf32r((xv.z - mu) * rstd * gv.z + bv.z);
    o4.w = tf32r((xv.w - mu) * rstd * gv.w + bv.w);
    *(float4*)(xn + (size_t)row * DM + tid * 4) = o4;
    float4 r4;
    r4.x = tf32r(xv.x); r4.y = tf32r(xv.y); r4.z = tf32r(xv.z); r4.w = tf32r(xv.w);
    *(float4*)(xr + (size_t)row * DM + tid * 4) = r4;
}

// ---------------- fused gate-normalize + head split + elu+1 ----------------
__global__ void gatesplit_kernel() {
    __shared__ float red[8];
    int n = blockIdx.x, tid = threadIdx.x;      // one token per block
    float4 gv = *(const float4*)(g_gate + (size_t)n * DM + tid * 4);
    float s = gv.x + gv.y + gv.z + gv.w;
    #pragma unroll
    for (int o = 16; o > 0; o >>= 1) s += __shfl_xor_sync(0xffffffffu, s, o);
    if ((tid & 31) == 0) red[tid >> 5] = s;
    __syncthreads();
    if (tid < 32) {
        s = (tid < 8) ? red[tid] : 0.f;
        #pragma unroll
        for (int o = 4; o > 0; o >>= 1) s += __shfl_xor_sync(0xffffffffu, s, o);
        if (tid == 0) red[0] = s;
    }
    __syncthreads();
    float scale = 1.f / (red[0] * (1.f / DM) + 1e-5f);

    int cix = tid * 4;
    int h = cix >> 6, e = cix & 63;
    int b = n >> 11, t = n & 2047;
    const float* qkv = g_qkv + (size_t)n * 3072;
    float4 q4 = *(const float4*)(qkv + cix);
    float4 k4 = *(const float4*)(qkv + 1024 + cix);
    float4 v4 = *(const float4*)(qkv + 2048 + cix);
    float gn0 = gv.x * scale, gn1 = gv.y * scale, gn2 = gv.z * scale, gn3 = gv.w * scale;
    q4.x *= gn0; q4.y *= gn1; q4.z *= gn2; q4.w *= gn3;
    k4.x *= gn0; k4.y *= gn1; k4.z *= gn2; k4.w *= gn3;
    q4.x = (q4.x > 0.f) ? q4.x + 1.f : expf(q4.x);
    q4.y = (q4.y > 0.f) ? q4.y + 1.f : expf(q4.y);
    q4.z = (q4.z > 0.f) ? q4.z + 1.f : expf(q4.z);
    q4.w = (q4.w > 0.f) ? q4.w + 1.f : expf(q4.w);
    k4.x = (k4.x > 0.f) ? k4.x + 1.f : expf(k4.x);
    k4.y = (k4.y > 0.f) ? k4.y + 1.f : expf(k4.y);
    k4.z = (k4.z > 0.f) ? k4.z + 1.f : expf(k4.z);
    k4.w = (k4.w > 0.f) ? k4.w + 1.f : expf(k4.w);
    size_t o = ((size_t)(b * NH + h) * SEQ + t) * DH + e;
    *(float4*)(g_qh + o) = q4;
    *(float4*)(g_kh + o) = k4;
    *(float4*)(g_vh + o) = v4;
}

// ---------------- pass A: per-chunk KV = k^T@v, ksum ----------------
__global__ void passA_kernel() {
    __shared__ float ks[64][64];
    __shared__ float vs[64][64];
    int blk = blockIdx.x;
    int bh = blk / NCH, c = blk % NCH;
    const float* kb = g_kh + ((size_t)bh * SEQ + c * CHUNK) * DH;
    const float* vb = g_vh + ((size_t)bh * SEQ + c * CHUNK) * DH;
    int tid = threadIdx.x;
    int d = tid & 63, mg = tid >> 6;
    float acc[16];
    #pragma unroll
    for (int i = 0; i < 16; i++) acc[i] = 0.f;
    float ksum = 0.f;
    for (int half = 0; half < 2; half++) {
        __syncthreads();
        #pragma unroll
        for (int l = 0; l < 4; l++) {
            int id = tid + l * 256;
            int r = id >> 4, c4 = (id & 15) * 4;
            *(float4*)&ks[r][c4] = *(const float4*)(kb + half * 64 * 64 + r * 64 + c4);
            *(float4*)&vs[r][c4] = *(const float4*)(vb + half * 64 * 64 + r * 64 + c4);
        }
        __syncthreads();
        #pragma unroll 4
        for (int t = 0; t < 64; t++) {
            float kd = ks[t][d];
            if (mg == 0) ksum += kd;
            #pragma unroll
            for (int i = 0; i < 16; i++) acc[i] += kd * vs[t][mg * 16 + i];
        }
    }
    float* kvo = g_kv + (size_t)blk * (DH * DH);
    #pragma unroll
    for (int i = 0; i < 16; i += 4)
        *(float4*)(kvo + d * 64 + mg * 16 + i) = make_float4(acc[i], acc[i+1], acc[i+2], acc[i+3]);
    if (mg == 0) g_ksum[blk * DH + d] = ksum;
}

// ---------------- pass B: exclusive prefix over chunks (512 blocks) ----------------
__global__ void passB_kernel() {
    int bh = blockIdx.y;
    int e = blockIdx.x * 256 + threadIdx.x;
    float run = 0.f;
    #pragma unroll
    for (int c = 0; c < NCH; c++) {
        size_t idx = ((size_t)bh * NCH + c) * (DH * DH) + e;
        g_kvpre[idx] = run;
        run += g_kv[idx];
    }
    if (blockIdx.x == 0 && threadIdx.x < DH) {
        float r2 = 0.f;
        #pragma unroll
        for (int c = 0; c < NCH; c++) {
            size_t idx = ((size_t)bh * NCH + c) * DH + threadIdx.x;
            g_kspre[idx] = r2;
            r2 += g_ksum[idx];
        }
    }
}

// ---------------- pass C (output rounded to tf32 for proj GEMM) ----------------
__global__ void passC_kernel() {
    extern __shared__ float smf[];
    float (*k_sm)[64] = (float(*)[64])smf;
    float (*v_sm)[64] = (float(*)[64])(smf + 128 * 64);
    float (*s_sm)[64] = (float(*)[64])(smf + 2 * 128 * 64);
    float* kp_sm = smf + 2 * 128 * 64 + 64 * 64;

    int blk = blockIdx.x;
    int bh = blk / NCH, c = blk % NCH;
    int b = bh / NH, h = bh % NH;
    int tid = threadIdx.x;
    const float* qb = g_qh + ((size_t)bh * SEQ + c * CHUNK) * DH;
    const float* kb = g_kh + ((size_t)bh * SEQ + c * CHUNK) * DH;
    const float* vb = g_vh + ((size_t)bh * SEQ + c * CHUNK) * DH;

    #pragma unroll
    for (int l = 0; l < 8; l++) {
        int id = tid + l * 256;
        int r = id >> 4, c4 = (id & 15) * 4;
        *(float4*)&k_sm[r][c4] = *(const float4*)(kb + r * 64 + c4);
        *(float4*)&v_sm[r][c4] = *(const float4*)(vb + r * 64 + c4);
    }
    #pragma unroll
    for (int l = 0; l < 4; l++) {
        int id = tid + l * 256;
        int r = id >> 4, c4 = (id & 15) * 4;
        *(float4*)&s_sm[r][c4] = *(const float4*)(g_kvpre + (size_t)blk * 4096 + r * 64 + c4);
    }
    if (tid < 64) kp_sm[tid] = g_kspre[(size_t)blk * 64 + tid];
    __syncthreads();

    int t = tid >> 1, half = tid & 1;
    float q[64];
    #pragma unroll
    for (int i = 0; i < 64; i += 4) {
        float4 qv = *(const float4*)(qb + t * 64 + i);
        q[i] = qv.x; q[i+1] = qv.y; q[i+2] = qv.z; q[i+3] = qv.w;
    }
    float acc[32];
    #pragma unroll
    for (int i = 0; i < 32; i++) acc[i] = 0.f;
    float den = 0.f;

    #pragma unroll 8
    for (int d = 0; d < 64; d++) {
        float qd = q[d];
        den += qd * kp_sm[d];
        #pragma unroll
        for (int i = 0; i < 32; i++) acc[i] += qd * s_sm[d][half + 2 * i];
    }
    for (int s = 0; s <= t; s++) {
        float a = 0.f;
        #pragma unroll
        for (int d = 0; d < 64; d++) a += q[d] * k_sm[s][d];
        den += a;
        #pragma unroll
        for (int i = 0; i < 32; i++) acc[i] += a * v_sm[s][half + 2 * i];
    }
    float inv = 1.f / (den + 1e-5f);
    int token = b * SEQ + c * CHUNK + t;
    float* outp = g_ctx + (size_t)token * DM + h * DH;
    #pragma unroll
    for (int i = 0; i < 32; i++) outp[half + 2 * i] = tf32r(acc[i] * inv);
}

// ---------------- launch ----------------
extern "C" void kernel_launch(void* const* d_in, const int* in_sizes, int n_in,
                              void* d_out, int out_size) {
    const float* x      = (const float*)d_in[0];
    const float* ln_g   = (const float*)d_in[1];
    const float* ln_b   = (const float*)d_in[2];
    const float* w_qkv  = (const float*)d_in[3];
    const float* b_qkv  = (const float*)d_in[4];
    const float* w_gate = (const float*)d_in[5];
    const float* b_gate = (const float*)d_in[6];
    const float* w_proj = (const float*)d_in[7];
    const float* b_proj = (const float*)d_in[8];
    float* out = (float*)d_out;

    float *p_xnorm, *p_xr, *p_qkv, *p_gate, *p_ctx, *p_wqkv, *p_wgate, *p_wproj;
    cudaGetSymbolAddress((void**)&p_xnorm, g_xnorm);
    cudaGetSymbolAddress((void**)&p_xr,    g_xr);
    cudaGetSymbolAddress((void**)&p_qkv,   g_qkv);
    cudaGetSymbolAddress((void**)&p_gate,  g_gate);
    cudaGetSymbolAddress((void**)&p_ctx,   g_ctx);
    cudaGetSymbolAddress((void**)&p_wqkv,  g_wqkv);
    cudaGetSymbolAddress((void**)&p_wgate, g_wgate);
    cudaGetSymbolAddress((void**)&p_wproj, g_wproj);

    const int smemC = (2 * 128 * 64 + 64 * 64 + 64) * 4;
    cudaFuncSetAttribute(passC_kernel, cudaFuncAttributeMaxDynamicSharedMemorySize, smemC);
    cudaFuncSetAttribute(mma_gemm<false>, cudaFuncAttributeMaxDynamicSharedMemorySize, GEMM_SMEM_BYTES);
    cudaFuncSetAttribute(mma_gemm<true>,  cudaFuncAttributeMaxDynamicSharedMemorySize, GEMM_SMEM_BYTES);

    // 0. round weights to tf32 copies
    round_kernel<<<(3 * DM * DM / 4) / 256, 256>>>(w_qkv, p_wqkv);
    round_kernel<<<(DM * DM / 4) / 256, 256>>>(w_gate, p_wgate);
    round_kernel<<<(DM * DM / 4) / 256, 256>>>(w_proj, p_wproj);
    // 1. LayerNorm (emits rounded xnorm + rounded x)
    ln_kernel<<<NTOK, 256>>>(x, ln_g, ln_b, p_xnorm, p_xr);
    // 2. qkv = xnorm @ w_qkv + b_qkv
    mma_gemm<false><<<dim3(3 * DM / 128, NTOK / 128), 128, GEMM_SMEM_BYTES>>>(p_xnorm, p_wqkv, b_qkv, p_qkv, NTOK, 3 * DM, DM);
    // 3. gate = sigmoid(x @ w_gate + b_gate)
    mma_gemm<true><<<dim3(DM / 128, NTOK / 128), 128, GEMM_SMEM_BYTES>>>(p_xr, p_wgate, b_gate, p_gate, NTOK, DM, DM);
    // 4+5. fused gate-normalize + split + elu+1
    gatesplit_kernel<<<NTOK, 256>>>();
    // 6-8. chunked causal linear attention
    passA_kernel<<<NBH * NCH, 256>>>();
    passB_kernel<<<dim3(16, NBH), 256>>>();
    passC_kernel<<<NBH * NCH, 256, smemC>>>();
    // 9. projection
    mma_gemm<false><<<dim3(DM / 128, NTOK / 128), 128, GEMM_SMEM_BYTES>>>(p_ctx, p_wproj, b_proj, out, NTOK, DM, DM);
}

// round 6
// speedup vs baseline: 2.8968x; 1.0876x over previous
#include <cuda_runtime.h>
#include <cuda_bf16.h>
#include <math.h>
#include <stdint.h>

// ---------------- problem constants ----------------
#define BATCH 2
#define SEQ   2048
#define DM    1024
#define NH    16
#define DH    64
#define NTOK  (BATCH*SEQ)        // 4096
#define CHUNK 128
#define NCH   (SEQ/CHUNK)        // 16
#define NBH   (BATCH*NH)         // 32

// ---------------- scratch (device globals; no allocs allowed) ----------------
__device__ float g_xnorm[NTOK*DM];
__device__ float g_xr   [NTOK*DM];
__device__ float g_qkv  [NTOK*3*DM];
__device__ float g_gate [NTOK*DM];
__device__ float g_qh   [NBH*SEQ*DH];
__device__ float g_kh   [NBH*SEQ*DH];
__device__ float g_vh   [NBH*SEQ*DH];
__device__ float g_kv   [NBH*NCH*DH*DH];
__device__ float g_kvpre[NBH*NCH*DH*DH];
__device__ float g_ksum [NBH*NCH*DH];
__device__ float g_kspre[NBH*NCH*DH];
__device__ float g_ctx  [NTOK*DM];
__device__ float g_wqkv [3*DM*DM];
__device__ float g_wgate[DM*DM];
__device__ float g_wproj[DM*DM];

// ---------------- helpers ----------------
__device__ __forceinline__ float tf32r(float x) {
    float y; asm("cvt.rna.tf32.f32 %0, %1;" : "=f"(y) : "f"(x)); return y;
}
__device__ __forceinline__ void mma_tf32(float* c, const uint32_t* a, const uint32_t* b) {
    asm volatile(
        "mma.sync.aligned.m16n8k8.row.col.f32.tf32.tf32.f32 "
        "{%0,%1,%2,%3}, {%4,%5,%6,%7}, {%8,%9}, {%0,%1,%2,%3};"
        : "+f"(c[0]), "+f"(c[1]), "+f"(c[2]), "+f"(c[3])
        : "r"(a[0]), "r"(a[1]), "r"(a[2]), "r"(a[3]), "r"(b[0]), "r"(b[1]));
}
__device__ __forceinline__ uint32_t smem_u32(const void* p) {
    uint32_t a;
    asm("{ .reg .u64 t; cvta.to.shared.u64 t, %1; cvt.u32.u64 %0, t; }" : "=r"(a) : "l"(p));
    return a;
}
__device__ __forceinline__ void cp16(uint32_t dst, const void* src) {
    asm volatile("cp.async.cg.shared.global [%0], [%1], 16;" :: "r"(dst), "l"(src));
}
#define CP_COMMIT() asm volatile("cp.async.commit_group;" ::: "memory")
#define CP_WAIT(n)  asm volatile("cp.async.wait_group %0;" :: "n"(n) : "memory")

// ================= tf32 mma.sync GEMM core =================
// CTA tile 128x128, BK=32, 128 threads (4 warps 2x2), warp tile 64x64, 3-stage cp.async
#define AST (128*36)             // A stage floats
#define BST (32*136)             // B stage floats
#define GEMM_SMEM_BYTES (3*(AST+BST)*4)   // 107520
#define NKT (DM/32)              // 32 k-tiles (K = 1024 for all GEMMs here)

// Computes one 128x128 tile: C[bm0.., bn0..] = A[bm0..,:] @ B[:, bn0..] + bias
__device__ __forceinline__ void gemm_tile(
    const float* __restrict__ A, const float* __restrict__ B,
    const float* __restrict__ bias, float* __restrict__ C,
    int N, int bm0, int bn0, bool sigmoid, float* smf) {

    uint32_t sA = smem_u32(smf);
    uint32_t sB = sA + 3 * AST * 4;
    int tid = threadIdx.x;
    int wid = tid >> 5, lane = tid & 31;
    int gid = lane >> 2, tig = lane & 3;
    int wm = (wid & 1) * 64, wn = (wid >> 1) * 64;

    float c[4][8][4];
    #pragma unroll
    for (int mf = 0; mf < 4; mf++)
        #pragma unroll
        for (int nf = 0; nf < 8; nf++)
            #pragma unroll
            for (int r = 0; r < 4; r++) c[mf][nf][r] = 0.f;

    auto stage = [&](int s, int kt) {
        const float* Ab = A + (size_t)bm0 * DM + kt * 32;
        const float* Bb = B + (size_t)(kt * 32) * N + bn0;
        uint32_t sAb = sA + s * (AST * 4);
        uint32_t sBb = sB + s * (BST * 4);
        #pragma unroll
        for (int l = 0; l < 8; l++) {
            int id = tid + l * 128;
            int m = id >> 3, kq = (id & 7) * 4;      // A: 128 x 32
            cp16(sAb + (m * 36 + kq) * 4, Ab + (size_t)m * DM + kq);
            int kr = id >> 5, nc = (id & 31) * 4;    // B: 32 x 128
            cp16(sBb + (kr * 136 + nc) * 4, Bb + (size_t)kr * N + nc);
        }
    };

    stage(0, 0); CP_COMMIT();
    stage(1, 1); CP_COMMIT();

    for (int kt = 0; kt < NKT; kt++) {
        if (kt + 1 < NKT) { CP_WAIT(1); } else { CP_WAIT(0); }
        __syncthreads();

        int buf = kt % 3;
        const float* As_ = smf + buf * AST;
        const float* Bs_ = smf + 3 * AST + buf * BST;
        #pragma unroll
        for (int ks = 0; ks < 4; ks++) {
            int kb = ks * 8;
            uint32_t a[4][4], b[8][2];
            #pragma unroll
            for (int mf = 0; mf < 4; mf++) {
                int mr = wm + mf * 16 + gid;
                a[mf][0] = __float_as_uint(As_[(mr    ) * 36 + kb + tig    ]);
                a[mf][1] = __float_as_uint(As_[(mr + 8) * 36 + kb + tig    ]);
                a[mf][2] = __float_as_uint(As_[(mr    ) * 36 + kb + tig + 4]);
                a[mf][3] = __float_as_uint(As_[(mr + 8) * 36 + kb + tig + 4]);
            }
            #pragma unroll
            for (int nf = 0; nf < 8; nf++) {
                int nb = wn + nf * 8 + gid;
                b[nf][0] = __float_as_uint(Bs_[(kb + tig    ) * 136 + nb]);
                b[nf][1] = __float_as_uint(Bs_[(kb + tig + 4) * 136 + nb]);
            }
            #pragma unroll
            for (int mf = 0; mf < 4; mf++)
                #pragma unroll
                for (int nf = 0; nf < 8; nf++)
                    mma_tf32(c[mf][nf], a[mf], b[nf]);
        }

        if (kt + 2 < NKT) { stage((kt + 2) % 3, kt + 2); CP_COMMIT(); }
    }

    // epilogue
    #pragma unroll
    for (int mf = 0; mf < 4; mf++) {
        int row = bm0 + wm + mf * 16 + gid;
        #pragma unroll
        for (int nf = 0; nf < 8; nf++) {
            int col = bn0 + wn + nf * 8 + tig * 2;
            float b0 = bias[col], b1 = bias[col + 1];
            float2 o0 = make_float2(c[mf][nf][0] + b0, c[mf][nf][1] + b1);
            float2 o1 = make_float2(c[mf][nf][2] + b0, c[mf][nf][3] + b1);
            if (sigmoid) {
                o0.x = 1.f / (1.f + expf(-o0.x)); o0.y = 1.f / (1.f + expf(-o0.y));
                o1.x = 1.f / (1.f + expf(-o1.x)); o1.y = 1.f / (1.f + expf(-o1.y));
            }
            *(float2*)(C + (size_t)row * N + col) = o0;
            *(float2*)(C + (size_t)(row + 8) * N + col) = o1;
        }
    }
}

// persistent dual-job GEMM: qkv tiles (768) then gate tiles (256)
#define QKV_TILES (32*24)
#define ALL_TILES (QKV_TILES + 32*8)

__global__ void __launch_bounds__(128)
mma_gemm_dual(const float* __restrict__ Aq, const float* __restrict__ Bq,
              const float* __restrict__ biasq, float* __restrict__ Cq,
              const float* __restrict__ Ag, const float* __restrict__ Bg,
              const float* __restrict__ biasg, float* __restrict__ Cg) {
    extern __shared__ float smf[];
    for (int tile = blockIdx.x; tile < ALL_TILES; tile += gridDim.x) {
        __syncthreads();   // protect smem reuse across tiles
        if (tile < QKV_TILES) {
            int bm = tile / 24, bn = tile % 24;
            gemm_tile(Aq, Bq, biasq, Cq, 3 * DM, bm * 128, bn * 128, false, smf);
        } else {
            int t2 = tile - QKV_TILES;
            int bm = t2 / 8, bn = t2 % 8;
            gemm_tile(Ag, Bg, biasg, Cg, DM, bm * 128, bn * 128, true, smf);
        }
    }
}

// single-job GEMM (projection)
__global__ void __launch_bounds__(128)
mma_gemm_single(const float* __restrict__ A, const float* __restrict__ B,
                const float* __restrict__ bias, float* __restrict__ C) {
    extern __shared__ float smf[];
    int bm = blockIdx.y, bn = blockIdx.x;
    gemm_tile(A, B, bias, C, DM, bm * 128, bn * 128, false, smf);
}

// ---------------- round fp32 -> tf32 copy ----------------
__global__ void round_kernel(const float* __restrict__ src, float* __restrict__ dst) {
    int i = blockIdx.x * blockDim.x + threadIdx.x;
    float4 v = ((const float4*)src)[i];
    v.x = tf32r(v.x); v.y = tf32r(v.y); v.z = tf32r(v.z); v.w = tf32r(v.w);
    ((float4*)dst)[i] = v;
}

// ---------------- LayerNorm: rounded xnorm + rounded x copy ----------------
__global__ void ln_kernel(const float* __restrict__ x, const float* __restrict__ g,
                          const float* __restrict__ bta, float* __restrict__ xn,
                          float* __restrict__ xr) {
    __shared__ float red0[8], red1[8];
    int row = blockIdx.x, tid = threadIdx.x;
    const float* xrp = x + (size_t)row * DM;
    float4 xv = *(const float4*)(xrp + tid * 4);
    float s  = xv.x + xv.y + xv.z + xv.w;
    float s2 = xv.x*xv.x + xv.y*xv.y + xv.z*xv.z + xv.w*xv.w;
    #pragma unroll
    for (int o = 16; o > 0; o >>= 1) {
        s  += __shfl_xor_sync(0xffffffffu, s,  o);
        s2 += __shfl_xor_sync(0xffffffffu, s2, o);
    }
    int w = tid >> 5;
    if ((tid & 31) == 0) { red0[w] = s; red1[w] = s2; }
    __syncthreads();
    if (tid < 32) {
        s  = (tid < 8) ? red0[tid] : 0.f;
        s2 = (tid < 8) ? red1[tid] : 0.f;
        #pragma unroll
        for (int o = 4; o > 0; o >>= 1) {
            s  += __shfl_xor_sync(0xffffffffu, s,  o);
            s2 += __shfl_xor_sync(0xffffffffu, s2, o);
        }
        if (tid == 0) { red0[0] = s; red1[0] = s2; }
    }
    __syncthreads();
    float mu   = red0[0] * (1.f / DM);
    float var  = red1[0] * (1.f / DM) - mu * mu;
    float rstd = rsqrtf(var + 1e-5f);
    float4 gv = *(const float4*)(g + tid * 4);
    float4 bv = *(const float4*)(bta + tid * 4);
    float4 o4;
    o4.x = tf32r((xv.x - mu) * rstd * gv.x + bv.x);
    o4.y = tf32r((xv.y - mu) * rstd * gv.y + bv.y);
    o4.z = tf32r((xv.z - mu) * rstd * gv.z + bv.z);
    o4.w = tf32r((xv.w - mu) * rstd * gv.w + bv.w);
    *(float4*)(xn + (size_t)row * DM + tid * 4) = o4;
    float4 r4;
    r4.x = tf32r(xv.x); r4.y = tf32r(xv.y); r4.z = tf32r(xv.z); r4.w = tf32r(xv.w);
    *(float4*)(xr + (size_t)row * DM + tid * 4) = r4;
}

// ---------------- fused gate-normalize + head split + elu+1 ----------------
__global__ void gatesplit_kernel() {
    __shared__ float red[8];
    int n = blockIdx.x, tid = threadIdx.x;
    float4 gv = *(const float4*)(g_gate + (size_t)n * DM + tid * 4);
    float s = gv.x + gv.y + gv.z + gv.w;
    #pragma unroll
    for (int o = 16; o > 0; o >>= 1) s += __shfl_xor_sync(0xffffffffu, s, o);
    if ((tid & 31) == 0) red[tid >> 5] = s;
    __syncthreads();
    if (tid < 32) {
        s = (tid < 8) ? red[tid] : 0.f;
        #pragma unroll
        for (int o = 4; o > 0; o >>= 1) s += __shfl_xor_sync(0xffffffffu, s, o);
        if (tid == 0) red[0] = s;
    }
    __syncthreads();
    float scale = 1.f / (red[0] * (1.f / DM) + 1e-5f);

    int cix = tid * 4;
    int h = cix >> 6, e = cix & 63;
    int b = n >> 11, t = n & 2047;
    const float* qkv = g_qkv + (size_t)n * 3072;
    float4 q4 = *(const float4*)(qkv + cix);
    float4 k4 = *(const float4*)(qkv + 1024 + cix);
    float4 v4 = *(const float4*)(qkv + 2048 + cix);
    float gn0 = gv.x * scale, gn1 = gv.y * scale, gn2 = gv.z * scale, gn3 = gv.w * scale;
    q4.x *= gn0; q4.y *= gn1; q4.z *= gn2; q4.w *= gn3;
    k4.x *= gn0; k4.y *= gn1; k4.z *= gn2; k4.w *= gn3;
    q4.x = (q4.x > 0.f) ? q4.x + 1.f : expf(q4.x);
    q4.y = (q4.y > 0.f) ? q4.y + 1.f : expf(q4.y);
    q4.z = (q4.z > 0.f) ? q4.z + 1.f : expf(q4.z);
    q4.w = (q4.w > 0.f) ? q4.w + 1.f : expf(q4.w);
    k4.x = (k4.x > 0.f) ? k4.x + 1.f : expf(k4.x);
    k4.y = (k4.y > 0.f) ? k4.y + 1.f : expf(k4.y);
    k4.z = (k4.z > 0.f) ? k4.z + 1.f : expf(k4.z);
    k4.w = (k4.w > 0.f) ? k4.w + 1.f : expf(k4.w);
    size_t o = ((size_t)(b * NH + h) * SEQ + t) * DH + e;
    *(float4*)(g_qh + o) = q4;
    *(float4*)(g_kh + o) = k4;
    *(float4*)(g_vh + o) = v4;
}

// ---------------- pass A: per-chunk KV = k^T@v, ksum ----------------
__global__ void passA_kernel() {
    __shared__ float ks[64][64];
    __shared__ float vs[64][64];
    int blk = blockIdx.x;
    int bh = blk / NCH, c = blk % NCH;
    const float* kb = g_kh + ((size_t)bh * SEQ + c * CHUNK) * DH;
    const float* vb = g_vh + ((size_t)bh * SEQ + c * CHUNK) * DH;
    int tid = threadIdx.x;
    int d = tid & 63, mg = tid >> 6;
    float acc[16];
    #pragma unroll
    for (int i = 0; i < 16; i++) acc[i] = 0.f;
    float ksum = 0.f;
    for (int half = 0; half < 2; half++) {
        __syncthreads();
        #pragma unroll
        for (int l = 0; l < 4; l++) {
            int id = tid + l * 256;
            int r = id >> 4, c4 = (id & 15) * 4;
            *(float4*)&ks[r][c4] = *(const float4*)(kb + half * 64 * 64 + r * 64 + c4);
            *(float4*)&vs[r][c4] = *(const float4*)(vb + half * 64 * 64 + r * 64 + c4);
        }
        __syncthreads();
        #pragma unroll 4
        for (int t = 0; t < 64; t++) {
            float kd = ks[t][d];
            if (mg == 0) ksum += kd;
            #pragma unroll
            for (int i = 0; i < 16; i++) acc[i] += kd * vs[t][mg * 16 + i];
        }
    }
    float* kvo = g_kv + (size_t)blk * (DH * DH);
    #pragma unroll
    for (int i = 0; i < 16; i += 4)
        *(float4*)(kvo + d * 64 + mg * 16 + i) = make_float4(acc[i], acc[i+1], acc[i+2], acc[i+3]);
    if (mg == 0) g_ksum[blk * DH + d] = ksum;
}

// ---------------- pass B: exclusive prefix over chunks ----------------
__global__ void passB_kernel() {
    int bh = blockIdx.y;
    int e = blockIdx.x * 256 + threadIdx.x;
    float run = 0.f;
    #pragma unroll
    for (int c = 0; c < NCH; c++) {
        size_t idx = ((size_t)bh * NCH + c) * (DH * DH) + e;
        g_kvpre[idx] = run;
        run += g_kv[idx];
    }
    if (blockIdx.x == 0 && threadIdx.x < DH) {
        float r2 = 0.f;
        #pragma unroll
        for (int c = 0; c < NCH; c++) {
            size_t idx = ((size_t)bh * NCH + c) * DH + threadIdx.x;
            g_kspre[idx] = r2;
            r2 += g_ksum[idx];
        }
    }
}

// ---------------- pass C (output rounded to tf32 for proj GEMM) ----------------
__global__ void passC_kernel() {
    extern __shared__ float smf[];
    float (*k_sm)[64] = (float(*)[64])smf;
    float (*v_sm)[64] = (float(*)[64])(smf + 128 * 64);
    float (*s_sm)[64] = (float(*)[64])(smf + 2 * 128 * 64);
    float* kp_sm = smf + 2 * 128 * 64 + 64 * 64;

    int blk = blockIdx.x;
    int bh = blk / NCH, c = blk % NCH;
    int b = bh / NH, h = bh % NH;
    int tid = threadIdx.x;
    const float* qb = g_qh + ((size_t)bh * SEQ + c * CHUNK) * DH;
    const float* kb = g_kh + ((size_t)bh * SEQ + c * CHUNK) * DH;
    const float* vb = g_vh + ((size_t)bh * SEQ + c * CHUNK) * DH;

    #pragma unroll
    for (int l = 0; l < 8; l++) {
        int id = tid + l * 256;
        int r = id >> 4, c4 = (id & 15) * 4;
        *(float4*)&k_sm[r][c4] = *(const float4*)(kb + r * 64 + c4);
        *(float4*)&v_sm[r][c4] = *(const float4*)(vb + r * 64 + c4);
    }
    #pragma unroll
    for (int l = 0; l < 4; l++) {
        int id = tid + l * 256;
        int r = id >> 4, c4 = (id & 15) * 4;
        *(float4*)&s_sm[r][c4] = *(const float4*)(g_kvpre + (size_t)blk * 4096 + r * 64 + c4);
    }
    if (tid < 64) kp_sm[tid] = g_kspre[(size_t)blk * 64 + tid];
    __syncthreads();

    int t = tid >> 1, half = tid & 1;
    float q[64];
    #pragma unroll
    for (int i = 0; i < 64; i += 4) {
        float4 qv = *(const float4*)(qb + t * 64 + i);
        q[i] = qv.x; q[i+1] = qv.y; q[i+2] = qv.z; q[i+3] = qv.w;
    }
    float acc[32];
    #pragma unroll
    for (int i = 0; i < 32; i++) acc[i] = 0.f;
    float den = 0.f;

    #pragma unroll 8
    for (int d = 0; d < 64; d++) {
        float qd = q[d];
        den += qd * kp_sm[d];
        #pragma unroll
        for (int i = 0; i < 32; i++) acc[i] += qd * s_sm[d][half + 2 * i];
    }
    for (int s = 0; s <= t; s++) {
        float a = 0.f;
        #pragma unroll
        for (int d = 0; d < 64; d++) a += q[d] * k_sm[s][d];
        den += a;
        #pragma unroll
        for (int i = 0; i < 32; i++) acc[i] += a * v_sm[s][half + 2 * i];
    }
    float inv = 1.f / (den + 1e-5f);
    int token = b * SEQ + c * CHUNK + t;
    float* outp = g_ctx + (size_t)token * DM + h * DH;
    #pragma unroll
    for (int i = 0; i < 32; i++) outp[half + 2 * i] = tf32r(acc[i] * inv);
}

// ---------------- launch ----------------
extern "C" void kernel_launch(void* const* d_in, const int* in_sizes, int n_in,
                              void* d_out, int out_size) {
    const float* x      = (const float*)d_in[0];
    const float* ln_g   = (const float*)d_in[1];
    const float* ln_b   = (const float*)d_in[2];
    const float* w_qkv  = (const float*)d_in[3];
    const float* b_qkv  = (const float*)d_in[4];
    const float* w_gate = (const float*)d_in[5];
    const float* b_gate = (const float*)d_in[6];
    const float* w_proj = (const float*)d_in[7];
    const float* b_proj = (const float*)d_in[8];
    float* out = (float*)d_out;

    float *p_xnorm, *p_xr, *p_qkv, *p_gate, *p_ctx, *p_wqkv, *p_wgate, *p_wproj;
    cudaGetSymbolAddress((void**)&p_xnorm, g_xnorm);
    cudaGetSymbolAddress((void**)&p_xr,    g_xr);
    cudaGetSymbolAddress((void**)&p_qkv,   g_qkv);
    cudaGetSymbolAddress((void**)&p_gate,  g_gate);
    cudaGetSymbolAddress((void**)&p_ctx,   g_ctx);
    cudaGetSymbolAddress((void**)&p_wqkv,  g_wqkv);
    cudaGetSymbolAddress((void**)&p_wgate, g_wgate);
    cudaGetSymbolAddress((void**)&p_wproj, g_wproj);

    const int smemC = (2 * 128 * 64 + 64 * 64 + 64) * 4;
    cudaFuncSetAttribute(passC_kernel, cudaFuncAttributeMaxDynamicSharedMemorySize, smemC);
    cudaFuncSetAttribute(mma_gemm_dual,   cudaFuncAttributeMaxDynamicSharedMemorySize, GEMM_SMEM_BYTES);
    cudaFuncSetAttribute(mma_gemm_single, cudaFuncAttributeMaxDynamicSharedMemorySize, GEMM_SMEM_BYTES);

    // 0. round weights to tf32 copies
    round_kernel<<<(3 * DM * DM / 4) / 256, 256>>>(w_qkv, p_wqkv);
    round_kernel<<<(DM * DM / 4) / 256, 256>>>(w_gate, p_wgate);
    round_kernel<<<(DM * DM / 4) / 256, 256>>>(w_proj, p_wproj);
    // 1. LayerNorm (emits rounded xnorm + rounded x)
    ln_kernel<<<NTOK, 256>>>(x, ln_g, ln_b, p_xnorm, p_xr);
    // 2+3. persistent dual GEMM: qkv then gate (gate tiles backfill qkv tail)
    mma_gemm_dual<<<296, 128, GEMM_SMEM_BYTES>>>(p_xnorm, p_wqkv, b_qkv, p_qkv,
                                                 p_xr, p_wgate, b_gate, p_gate);
    // 4+5. fused gate-normalize + split + elu+1
    gatesplit_kernel<<<NTOK, 256>>>();
    // 6-8. chunked causal linear attention
    passA_kernel<<<NBH * NCH, 256>>>();
    passB_kernel<<<dim3(16, NBH), 256>>>();
    passC_kernel<<<NBH * NCH, 256, smemC>>>();
    // 9. projection
    mma_gemm_single<<<dim3(DM / 128, NTOK / 128), 128, GEMM_SMEM_BYTES>>>(p_ctx, p_wproj, b_proj, out);
}

// round 7
// speedup vs baseline: 2.9210x; 1.0083x over previous
#include <cuda_runtime.h>
#include <cuda_bf16.h>
#include <math.h>
#include <stdint.h>

// ---------------- problem constants ----------------
#define BATCH 2
#define SEQ   2048
#define DM    1024
#define NH    16
#define DH    64
#define NTOK  (BATCH*SEQ)        // 4096
#define CHUNK 128
#define NCH   (SEQ/CHUNK)        // 16
#define NBH   (BATCH*NH)         // 32

// ---------------- scratch (device globals; no allocs allowed) ----------------
__device__ float g_xnorm[NTOK*DM];
__device__ float g_xr   [NTOK*DM];
__device__ float g_qkv  [NTOK*3*DM];
__device__ float g_gate [NTOK*DM];
__device__ float g_qh   [NBH*SEQ*DH];
__device__ float g_kh   [NBH*SEQ*DH];
__device__ float g_vh   [NBH*SEQ*DH];
__device__ float g_kv   [NBH*NCH*DH*DH];
__device__ float g_kvpre[NBH*NCH*DH*DH];
__device__ float g_ksum [NBH*NCH*DH];
__device__ float g_kspre[NBH*NCH*DH];
__device__ float g_ctx  [NTOK*DM];
__device__ float g_wqkv [3*DM*DM];
__device__ float g_wgate[DM*DM];
__device__ float g_wproj[DM*DM];

// ---------------- helpers ----------------
__device__ __forceinline__ float tf32r(float x) {
    float y; asm("cvt.rna.tf32.f32 %0, %1;" : "=f"(y) : "f"(x)); return y;
}
__device__ __forceinline__ void mma_tf32(float* c, const uint32_t* a, const uint32_t* b) {
    asm volatile(
        "mma.sync.aligned.m16n8k8.row.col.f32.tf32.tf32.f32 "
        "{%0,%1,%2,%3}, {%4,%5,%6,%7}, {%8,%9}, {%0,%1,%2,%3};"
        : "+f"(c[0]), "+f"(c[1]), "+f"(c[2]), "+f"(c[3])
        : "r"(a[0]), "r"(a[1]), "r"(a[2]), "r"(a[3]), "r"(b[0]), "r"(b[1]));
}
__device__ __forceinline__ uint32_t smem_u32(const void* p) {
    uint32_t a;
    asm("{ .reg .u64 t; cvta.to.shared.u64 t, %1; cvt.u32.u64 %0, t; }" : "=r"(a) : "l"(p));
    return a;
}
__device__ __forceinline__ void cp16(uint32_t dst, const void* src) {
    asm volatile("cp.async.cg.shared.global [%0], [%1], 16;" :: "r"(dst), "l"(src));
}
#define CP_COMMIT() asm volatile("cp.async.commit_group;" ::: "memory")
#define CP_WAIT(n)  asm volatile("cp.async.wait_group %0;" :: "n"(n) : "memory")

// ================= tf32 mma.sync GEMM core =================
// CTA tile 128x128, BK=32, 128 threads (4 warps 2x2), warp tile 64x64, 3-stage cp.async
#define AST (128*36)             // A stage floats
#define BST (32*136)             // B stage floats
#define GEMM_SMEM_BYTES (3*(AST+BST)*4)   // 107520
#define NKT (DM/32)              // 32 k-tiles (K = 1024 for all GEMMs here)

__device__ __forceinline__ void gemm_tile(
    const float* __restrict__ A, const float* __restrict__ B,
    const float* __restrict__ bias, float* __restrict__ C,
    int N, int bm0, int bn0, bool sigmoid, float* smf) {

    uint32_t sA = smem_u32(smf);
    uint32_t sB = sA + 3 * AST * 4;
    int tid = threadIdx.x;
    int wid = tid >> 5, lane = tid & 31;
    int gid = lane >> 2, tig = lane & 3;
    int wm = (wid & 1) * 64, wn = (wid >> 1) * 64;

    float c[4][8][4];
    #pragma unroll
    for (int mf = 0; mf < 4; mf++)
        #pragma unroll
        for (int nf = 0; nf < 8; nf++)
            #pragma unroll
            for (int r = 0; r < 4; r++) c[mf][nf][r] = 0.f;

    auto stage = [&](int s, int kt) {
        const float* Ab = A + (size_t)bm0 * DM + kt * 32;
        const float* Bb = B + (size_t)(kt * 32) * N + bn0;
        uint32_t sAb = sA + s * (AST * 4);
        uint32_t sBb = sB + s * (BST * 4);
        #pragma unroll
        for (int l = 0; l < 8; l++) {
            int id = tid + l * 128;
            int m = id >> 3, kq = (id & 7) * 4;      // A: 128 x 32
            cp16(sAb + (m * 36 + kq) * 4, Ab + (size_t)m * DM + kq);
            int kr = id >> 5, nc = (id & 31) * 4;    // B: 32 x 128
            cp16(sBb + (kr * 136 + nc) * 4, Bb + (size_t)kr * N + nc);
        }
    };

    stage(0, 0); CP_COMMIT();
    stage(1, 1); CP_COMMIT();

    for (int kt = 0; kt < NKT; kt++) {
        if (kt + 1 < NKT) { CP_WAIT(1); } else { CP_WAIT(0); }
        __syncthreads();

        int buf = kt % 3;
        const float* As_ = smf + buf * AST;
        const float* Bs_ = smf + 3 * AST + buf * BST;
        #pragma unroll
        for (int ks = 0; ks < 4; ks++) {
            int kb = ks * 8;
            uint32_t a[4][4], b[8][2];
            #pragma unroll
            for (int mf = 0; mf < 4; mf++) {
                int mr = wm + mf * 16 + gid;
                a[mf][0] = __float_as_uint(As_[(mr    ) * 36 + kb + tig    ]);
                a[mf][1] = __float_as_uint(As_[(mr + 8) * 36 + kb + tig    ]);
                a[mf][2] = __float_as_uint(As_[(mr    ) * 36 + kb + tig + 4]);
                a[mf][3] = __float_as_uint(As_[(mr + 8) * 36 + kb + tig + 4]);
            }
            #pragma unroll
            for (int nf = 0; nf < 8; nf++) {
                int nb = wn + nf * 8 + gid;
                b[nf][0] = __float_as_uint(Bs_[(kb + tig    ) * 136 + nb]);
                b[nf][1] = __float_as_uint(Bs_[(kb + tig + 4) * 136 + nb]);
            }
            #pragma unroll
            for (int mf = 0; mf < 4; mf++)
                #pragma unroll
                for (int nf = 0; nf < 8; nf++)
                    mma_tf32(c[mf][nf], a[mf], b[nf]);
        }

        if (kt + 2 < NKT) { stage((kt + 2) % 3, kt + 2); CP_COMMIT(); }
    }

    // epilogue
    #pragma unroll
    for (int mf = 0; mf < 4; mf++) {
        int row = bm0 + wm + mf * 16 + gid;
        #pragma unroll
        for (int nf = 0; nf < 8; nf++) {
            int col = bn0 + wn + nf * 8 + tig * 2;
            float b0 = bias[col], b1 = bias[col + 1];
            float2 o0 = make_float2(c[mf][nf][0] + b0, c[mf][nf][1] + b1);
            float2 o1 = make_float2(c[mf][nf][2] + b0, c[mf][nf][3] + b1);
            if (sigmoid) {
                o0.x = 1.f / (1.f + expf(-o0.x)); o0.y = 1.f / (1.f + expf(-o0.y));
                o1.x = 1.f / (1.f + expf(-o1.x)); o1.y = 1.f / (1.f + expf(-o1.y));
            }
            *(float2*)(C + (size_t)row * N + col) = o0;
            *(float2*)(C + (size_t)(row + 8) * N + col) = o1;
        }
    }
}

// persistent dual-job GEMM: qkv tiles (768) then gate tiles (256)
#define QKV_TILES (32*24)
#define ALL_TILES (QKV_TILES + 32*8)

__global__ void __launch_bounds__(128, 2)
mma_gemm_dual(const float* __restrict__ Aq, const float* __restrict__ Bq,
              const float* __restrict__ biasq, float* __restrict__ Cq,
              const float* __restrict__ Ag, const float* __restrict__ Bg,
              const float* __restrict__ biasg, float* __restrict__ Cg) {
    extern __shared__ float smf[];
    for (int tile = blockIdx.x; tile < ALL_TILES; tile += gridDim.x) {
        __syncthreads();   // protect smem reuse across tiles
        if (tile < QKV_TILES) {
            int bm = tile / 24, bn = tile % 24;
            gemm_tile(Aq, Bq, biasq, Cq, 3 * DM, bm * 128, bn * 128, false, smf);
        } else {
            int t2 = tile - QKV_TILES;
            int bm = t2 / 8, bn = t2 % 8;
            gemm_tile(Ag, Bg, biasg, Cg, DM, bm * 128, bn * 128, true, smf);
        }
    }
}

// single-job GEMM (projection)
__global__ void __launch_bounds__(128, 2)
mma_gemm_single(const float* __restrict__ A, const float* __restrict__ B,
                const float* __restrict__ bias, float* __restrict__ C) {
    extern __shared__ float smf[];
    int bm = blockIdx.y, bn = blockIdx.x;
    gemm_tile(A, B, bias, C, DM, bm * 128, bn * 128, false, smf);
}

// ---------------- round fp32 -> tf32: all three weight matrices in one launch ----------------
#define RND_QKV (3*DM*DM/4)      // float4 counts
#define RND_G   (DM*DM/4)
__global__ void round_all_kernel(const float* __restrict__ wq, const float* __restrict__ wg,
                                 const float* __restrict__ wp) {
    int i = blockIdx.x * blockDim.x + threadIdx.x;
    const float4* src;
    float4* dst;
    int j = i;
    if (j < RND_QKV) {
        src = (const float4*)wq; dst = (float4*)g_wqkv;
    } else if ((j -= RND_QKV) < RND_G) {
        src = (const float4*)wg; dst = (float4*)g_wgate;
    } else {
        j -= RND_G;
        src = (const float4*)wp; dst = (float4*)g_wproj;
    }
    float4 v = src[j];
    v.x = tf32r(v.x); v.y = tf32r(v.y); v.z = tf32r(v.z); v.w = tf32r(v.w);
    dst[j] = v;
}

// ---------------- LayerNorm: rounded xnorm + rounded x copy ----------------
__global__ void ln_kernel(const float* __restrict__ x, const float* __restrict__ g,
                          const float* __restrict__ bta, float* __restrict__ xn,
                          float* __restrict__ xr) {
    __shared__ float red0[8], red1[8];
    int row = blockIdx.x, tid = threadIdx.x;
    const float* xrp = x + (size_t)row * DM;
    float4 xv = *(const float4*)(xrp + tid * 4);
    float s  = xv.x + xv.y + xv.z + xv.w;
    float s2 = xv.x*xv.x + xv.y*xv.y + xv.z*xv.z + xv.w*xv.w;
    #pragma unroll
    for (int o = 16; o > 0; o >>= 1) {
        s  += __shfl_xor_sync(0xffffffffu, s,  o);
        s2 += __shfl_xor_sync(0xffffffffu, s2, o);
    }
    int w = tid >> 5;
    if ((tid & 31) == 0) { red0[w] = s; red1[w] = s2; }
    __syncthreads();
    if (tid < 32) {
        s  = (tid < 8) ? red0[tid] : 0.f;
        s2 = (tid < 8) ? red1[tid] : 0.f;
        #pragma unroll
        for (int o = 4; o > 0; o >>= 1) {
            s  += __shfl_xor_sync(0xffffffffu, s,  o);
            s2 += __shfl_xor_sync(0xffffffffu, s2, o);
        }
        if (tid == 0) { red0[0] = s; red1[0] = s2; }
    }
    __syncthreads();
    float mu   = red0[0] * (1.f / DM);
    float var  = red1[0] * (1.f / DM) - mu * mu;
    float rstd = rsqrtf(var + 1e-5f);
    float4 gv = *(const float4*)(g + tid * 4);
    float4 bv = *(const float4*)(bta + tid * 4);
    float4 o4;
    o4.x = tf32r((xv.x - mu) * rstd * gv.x + bv.x);
    o4.y = tf32r((xv.y - mu) * rstd * gv.y + bv.y);
    o4.z = tf32r((xv.z - mu) * rstd * gv.z + bv.z);
    o4.w = tf32r((xv.w - mu) * rstd * gv.w + bv.w);
    *(float4*)(xn + (size_t)row * DM + tid * 4) = o4;
    float4 r4;
    r4.x = tf32r(xv.x); r4.y = tf32r(xv.y); r4.z = tf32r(xv.z); r4.w = tf32r(xv.w);
    *(float4*)(xr + (size_t)row * DM + tid * 4) = r4;
}

// ---------------- fused gate-normalize + head split + elu+1 ----------------
__global__ void gatesplit_kernel() {
    __shared__ float red[8];
    int n = blockIdx.x, tid = threadIdx.x;
    float4 gv = *(const float4*)(g_gate + (size_t)n * DM + tid * 4);
    float s = gv.x + gv.y + gv.z + gv.w;
    #pragma unroll
    for (int o = 16; o > 0; o >>= 1) s += __shfl_xor_sync(0xffffffffu, s, o);
    if ((tid & 31) == 0) red[tid >> 5] = s;
    __syncthreads();
    if (tid < 32) {
        s = (tid < 8) ? red[tid] : 0.f;
        #pragma unroll
        for (int o = 4; o > 0; o >>= 1) s += __shfl_xor_sync(0xffffffffu, s, o);
        if (tid == 0) red[0] = s;
    }
    __syncthreads();
    float scale = 1.f / (red[0] * (1.f / DM) + 1e-5f);

    int cix = tid * 4;
    int h = cix >> 6, e = cix & 63;
    int b = n >> 11, t = n & 2047;
    const float* qkv = g_qkv + (size_t)n * 3072;
    float4 q4 = *(const float4*)(qkv + cix);
    float4 k4 = *(const float4*)(qkv + 1024 + cix);
    float4 v4 = *(const float4*)(qkv + 2048 + cix);
    float gn0 = gv.x * scale, gn1 = gv.y * scale, gn2 = gv.z * scale, gn3 = gv.w * scale;
    q4.x *= gn0; q4.y *= gn1; q4.z *= gn2; q4.w *= gn3;
    k4.x *= gn0; k4.y *= gn1; k4.z *= gn2; k4.w *= gn3;
    q4.x = (q4.x > 0.f) ? q4.x + 1.f : expf(q4.x);
    q4.y = (q4.y > 0.f) ? q4.y + 1.f : expf(q4.y);
    q4.z = (q4.z > 0.f) ? q4.z + 1.f : expf(q4.z);
    q4.w = (q4.w > 0.f) ? q4.w + 1.f : expf(q4.w);
    k4.x = (k4.x > 0.f) ? k4.x + 1.f : expf(k4.x);
    k4.y = (k4.y > 0.f) ? k4.y + 1.f : expf(k4.y);
    k4.z = (k4.z > 0.f) ? k4.z + 1.f : expf(k4.z);
    k4.w = (k4.w > 0.f) ? k4.w + 1.f : expf(k4.w);
    size_t o = ((size_t)(b * NH + h) * SEQ + t) * DH + e;
    *(float4*)(g_qh + o) = q4;
    *(float4*)(g_kh + o) = k4;
    *(float4*)(g_vh + o) = v4;
}

// ---------------- pass A: per-chunk KV = k^T@v, ksum ----------------
__global__ void passA_kernel() {
    __shared__ float ks[64][64];
    __shared__ float vs[64][64];
    int blk = blockIdx.x;
    int bh = blk / NCH, c = blk % NCH;
    const float* kb = g_kh + ((size_t)bh * SEQ + c * CHUNK) * DH;
    const float* vb = g_vh + ((size_t)bh * SEQ + c * CHUNK) * DH;
    int tid = threadIdx.x;
    int d = tid & 63, mg = tid >> 6;
    float acc[16];
    #pragma unroll
    for (int i = 0; i < 16; i++) acc[i] = 0.f;
    float ksum = 0.f;
    for (int half = 0; half < 2; half++) {
        __syncthreads();
        #pragma unroll
        for (int l = 0; l < 4; l++) {
            int id = tid + l * 256;
            int r = id >> 4, c4 = (id & 15) * 4;
            *(float4*)&ks[r][c4] = *(const float4*)(kb + half * 64 * 64 + r * 64 + c4);
            *(float4*)&vs[r][c4] = *(const float4*)(vb + half * 64 * 64 + r * 64 + c4);
        }
        __syncthreads();
        #pragma unroll 4
        for (int t = 0; t < 64; t++) {
            float kd = ks[t][d];
            if (mg == 0) ksum += kd;
            #pragma unroll
            for (int i = 0; i < 16; i++) acc[i] += kd * vs[t][mg * 16 + i];
        }
    }
    float* kvo = g_kv + (size_t)blk * (DH * DH);
    #pragma unroll
    for (int i = 0; i < 16; i += 4)
        *(float4*)(kvo + d * 64 + mg * 16 + i) = make_float4(acc[i], acc[i+1], acc[i+2], acc[i+3]);
    if (mg == 0) g_ksum[blk * DH + d] = ksum;
}

// ---------------- pass B: exclusive prefix over chunks ----------------
__global__ void passB_kernel() {
    int bh = blockIdx.y;
    int e = blockIdx.x * 256 + threadIdx.x;
    float run = 0.f;
    #pragma unroll
    for (int c = 0; c < NCH; c++) {
        size_t idx = ((size_t)bh * NCH + c) * (DH * DH) + e;
        g_kvpre[idx] = run;
        run += g_kv[idx];
    }
    if (blockIdx.x == 0 && threadIdx.x < DH) {
        float r2 = 0.f;
        #pragma unroll
        for (int c = 0; c < NCH; c++) {
            size_t idx = ((size_t)bh * NCH + c) * DH + threadIdx.x;
            g_kspre[idx] = r2;
            r2 += g_ksum[idx];
        }
    }
}

// ---------------- pass C (output rounded to tf32 for proj GEMM) ----------------
__global__ void passC_kernel() {
    extern __shared__ float smf[];
    float (*k_sm)[64] = (float(*)[64])smf;
    float (*v_sm)[64] = (float(*)[64])(smf + 128 * 64);
    float (*s_sm)[64] = (float(*)[64])(smf + 2 * 128 * 64);
    float* kp_sm = smf + 2 * 128 * 64 + 64 * 64;

    int blk = blockIdx.x;
    int bh = blk / NCH, c = blk % NCH;
    int b = bh / NH, h = bh % NH;
    int tid = threadIdx.x;
    const float* qb = g_qh + ((size_t)bh * SEQ + c * CHUNK) * DH;
    const float* kb = g_kh + ((size_t)bh * SEQ + c * CHUNK) * DH;
    const float* vb = g_vh + ((size_t)bh * SEQ + c * CHUNK) * DH;

    #pragma unroll
    for (int l = 0; l < 8; l++) {
        int id = tid + l * 256;
        int r = id >> 4, c4 = (id & 15) * 4;
        *(float4*)&k_sm[r][c4] = *(const float4*)(kb + r * 64 + c4);
        *(float4*)&v_sm[r][c4] = *(const float4*)(vb + r * 64 + c4);
    }
    #pragma unroll
    for (int l = 0; l < 4; l++) {
        int id = tid + l * 256;
        int r = id >> 4, c4 = (id & 15) * 4;
        *(float4*)&s_sm[r][c4] = *(const float4*)(g_kvpre + (size_t)blk * 4096 + r * 64 + c4);
    }
    if (tid < 64) kp_sm[tid] = g_kspre[(size_t)blk * 64 + tid];
    __syncthreads();

    int t = tid >> 1, half = tid & 1;
    float q[64];
    #pragma unroll
    for (int i = 0; i < 64; i += 4) {
        float4 qv = *(const float4*)(qb + t * 64 + i);
        q[i] = qv.x; q[i+1] = qv.y; q[i+2] = qv.z; q[i+3] = qv.w;
    }
    float acc[32];
    #pragma unroll
    for (int i = 0; i < 32; i++) acc[i] = 0.f;
    float den = 0.f;

    #pragma unroll 8
    for (int d = 0; d < 64; d++) {
        float qd = q[d];
        den += qd * kp_sm[d];
        #pragma unroll
        for (int i = 0; i < 32; i++) acc[i] += qd * s_sm[d][half + 2 * i];
    }
    for (int s = 0; s <= t; s++) {
        float a = 0.f;
        #pragma unroll
        for (int d = 0; d < 64; d++) a += q[d] * k_sm[s][d];
        den += a;
        #pragma unroll
        for (int i = 0; i < 32; i++) acc[i] += a * v_sm[s][half + 2 * i];
    }
    float inv = 1.f / (den + 1e-5f);
    int token = b * SEQ + c * CHUNK + t;
    float* outp = g_ctx + (size_t)token * DM + h * DH;
    #pragma unroll
    for (int i = 0; i < 32; i++) outp[half + 2 * i] = tf32r(acc[i] * inv);
}

// ---------------- launch ----------------
extern "C" void kernel_launch(void* const* d_in, const int* in_sizes, int n_in,
                              void* d_out, int out_size) {
    const float* x      = (const float*)d_in[0];
    const float* ln_g   = (const float*)d_in[1];
    const float* ln_b   = (const float*)d_in[2];
    const float* w_qkv  = (const float*)d_in[3];
    const float* b_qkv  = (const float*)d_in[4];
    const float* w_gate = (const float*)d_in[5];
    const float* b_gate = (const float*)d_in[6];
    const float* w_proj = (const float*)d_in[7];
    const float* b_proj = (const float*)d_in[8];
    float* out = (float*)d_out;

    float *p_xnorm, *p_xr, *p_qkv, *p_gate, *p_ctx, *p_wqkv, *p_wgate, *p_wproj;
    cudaGetSymbolAddress((void**)&p_xnorm, g_xnorm);
    cudaGetSymbolAddress((void**)&p_xr,    g_xr);
    cudaGetSymbolAddress((void**)&p_qkv,   g_qkv);
    cudaGetSymbolAddress((void**)&p_gate,  g_gate);
    cudaGetSymbolAddress((void**)&p_ctx,   g_ctx);
    cudaGetSymbolAddress((void**)&p_wqkv,  g_wqkv);
    cudaGetSymbolAddress((void**)&p_wgate, g_wgate);
    cudaGetSymbolAddress((void**)&p_wproj, g_wproj);

    const int smemC = (2 * 128 * 64 + 64 * 64 + 64) * 4;
    cudaFuncSetAttribute(passC_kernel, cudaFuncAttributeMaxDynamicSharedMemorySize, smemC);
    cudaFuncSetAttribute(mma_gemm_dual,   cudaFuncAttributeMaxDynamicSharedMemorySize, GEMM_SMEM_BYTES);
    cudaFuncSetAttribute(mma_gemm_single, cudaFuncAttributeMaxDynamicSharedMemorySize, GEMM_SMEM_BYTES);

    // 0. round weights to tf32 copies (single launch)
    round_all_kernel<<<(RND_QKV + 2 * RND_G) / 256, 256>>>(w_qkv, w_gate, w_proj);
    // 1. LayerNorm (emits rounded xnorm + rounded x)
    ln_kernel<<<NTOK, 256>>>(x, ln_g, ln_b, p_xnorm, p_xr);
    // 2+3. persistent dual GEMM: qkv then gate (gate tiles backfill qkv tail)
    mma_gemm_dual<<<296, 128, GEMM_SMEM_BYTES>>>(p_xnorm, p_wqkv, b_qkv, p_qkv,
                                                 p_xr, p_wgate, b_gate, p_gate);
    // 4+5. fused gate-normalize + split + elu+1
    gatesplit_kernel<<<NTOK, 256>>>();
    // 6-8. chunked causal linear attention
    passA_kernel<<<NBH * NCH, 256>>>();
    passB_kernel<<<dim3(16, NBH), 256>>>();
    passC_kernel<<<NBH * NCH, 256, smemC>>>();
    // 9. projection
    mma_gemm_single<<<dim3(DM / 128, NTOK / 128), 128, GEMM_SMEM_BYTES>>>(p_ctx, p_wproj, b_proj, out);
}